// round 9
// baseline (speedup 1.0000x reference)
#include <cuda_runtime.h>
#include <cuda_bf16.h>
#include <cstddef>

// Problem constants
#define BB 2
#define TT 2048
#define CC 1024
#define NHH 16
#define HDD 64
#define FFF 4096
#define MM (BB*TT)   // 4096

// ---------------------------------------------------------------------------
// Scratch (static device arrays — allocation-free per harness rules)
// ---------------------------------------------------------------------------
__device__ float g_h [MM*CC];   // LN1 output
__device__ float g_q [MM*CC];
__device__ float g_k [MM*CC];
__device__ float g_v [MM*CC];
__device__ float g_o [MM*CC];   // attention output, [B,T,C] layout
__device__ float g_x1[MM*CC];   // x + attn proj (residual 1)
__device__ float g_h2[MM*CC];   // LN2 output
__device__ float g_ff[MM*FFF];  // relu(h2@W1+b1)

// ---------------------------------------------------------------------------
// Packed fp32x2 helpers. FFMA2 = 4 FLOP/issue at rt_SMSP=2.
// Operand marshalling is done via smem layout (A duplicated in smem, B read
// as u64 pairs) so the inner loop is pure LDS.128 + FFMA2 — no MOVs.
// ---------------------------------------------------------------------------
__device__ __forceinline__ void ffma2(unsigned long long& d,
                                      unsigned long long a,
                                      unsigned long long b) {
    asm("fma.rn.f32x2 %0, %1, %2, %0;" : "+l"(d) : "l"(a), "l"(b));
}
__device__ __forceinline__ float2 unpk2(unsigned long long v) {
    float2 f;
    asm("mov.b64 {%0, %1}, %2;" : "=f"(f.x), "=f"(f.y) : "l"(v));
    return f;
}

// ---------------------------------------------------------------------------
// LayerNorm: one block per row, 256 threads, C=1024 (4 floats / thread)
// ---------------------------------------------------------------------------
__global__ __launch_bounds__(256) void ln_kernel(
    const float* __restrict__ x, const float* __restrict__ w,
    const float* __restrict__ bb, float* __restrict__ out)
{
    const int row = blockIdx.x;
    const int tid = threadIdx.x;
    const float* xr = x + (size_t)row * CC;
    float4 xv = ((const float4*)xr)[tid];

    float s  = xv.x + xv.y + xv.z + xv.w;
    float sq = xv.x*xv.x + xv.y*xv.y + xv.z*xv.z + xv.w*xv.w;

    #pragma unroll
    for (int m = 16; m > 0; m >>= 1) {
        s  += __shfl_xor_sync(0xffffffffu, s,  m);
        sq += __shfl_xor_sync(0xffffffffu, sq, m);
    }
    __shared__ float ss[8], ssq[8];
    const int lane = tid & 31, wid = tid >> 5;
    if (lane == 0) { ss[wid] = s; ssq[wid] = sq; }
    __syncthreads();
    float ts = 0.f, tsq = 0.f;
    #pragma unroll
    for (int i = 0; i < 8; i++) { ts += ss[i]; tsq += ssq[i]; }

    const float mu  = ts * (1.0f / CC);
    const float var = tsq * (1.0f / CC) - mu * mu;
    const float rs  = rsqrtf(var + 1e-5f);

    float4 wv = ((const float4*)w)[tid];
    float4 bv = ((const float4*)bb)[tid];
    float4 ov;
    ov.x = (xv.x - mu) * rs * wv.x + bv.x;
    ov.y = (xv.y - mu) * rs * wv.y + bv.y;
    ov.z = (xv.z - mu) * rs * wv.z + bv.z;
    ov.w = (xv.w - mu) * rs * wv.w + bv.w;
    ((float4*)(out + (size_t)row * CC))[tid] = ov;
}

// ---------------------------------------------------------------------------
// SGEMM core: C[M,N] = A[M,K] @ B[K,N] (+bias) (+resid) (relu?)
// 128x128 tile, BK=16, 8x8 per thread as 8x4 f32x2 pairs, 256 threads.
// Smem: As2 = A transposed AND duplicated along M (As2[kk][2m]=As2[kk][2m+1]
//       =A[m][kk]) so LDS.128 yields FFMA2-ready duplicated pairs.
//       Bs read as ulonglong2 -> natural f32x2 pairs. Inner loop: 6 LDS + 32 FFMA2.
// Dynamic smem: 2*16*264 + 2*16*128 floats = 50176 bytes, double buffered.
// ---------------------------------------------------------------------------
#define AS_STRIDE 264          // 256 duplicated floats + 8 pad
#define AS_BUF    (16 * AS_STRIDE)
#define BS_BUF    (16 * 128)
#define SGEMM_SMEM ((2 * AS_BUF + 2 * BS_BUF) * 4)   // 50176 bytes

__device__ __forceinline__ void sgemm_core(
    const float* __restrict__ A, const float* __restrict__ B,
    const float* __restrict__ bias, const float* __restrict__ resid,
    float* __restrict__ Cmat, int N, int K, int do_relu,
    int bm, int bn, float* sm)
{
    float* As2 = sm;                 // [2][16][264]
    float* Bs  = sm + 2 * AS_BUF;    // [2][16][128]

    const int tid = threadIdx.x;
    const int tx = tid & 15;
    const int ty = tid >> 4;

    const float* Ab = A + (size_t)bm * 128 * K;
    const float* Bb = B + (size_t)bn * 128;

    const int a_r0 = tid >> 2,           a_c0 = (tid & 3) << 2;
    const int a_r1 = a_r0 + 64;
    const int b_r0 = tid >> 5,           b_c0 = (tid & 31) << 2;
    const int b_r1 = b_r0 + 8;

    unsigned long long acc2[8][4];
    #pragma unroll
    for (int i = 0; i < 8; i++)
        #pragma unroll
        for (int j = 0; j < 4; j++) acc2[i][j] = 0ull;

    float4 a_st0, a_st1, b_st0, b_st1;

    // prologue: tile 0 -> buffer 0
    a_st0 = *(const float4*)(Ab + (size_t)a_r0 * K + a_c0);
    a_st1 = *(const float4*)(Ab + (size_t)a_r1 * K + a_c0);
    b_st0 = *(const float4*)(Bb + (size_t)b_r0 * N + b_c0);
    b_st1 = *(const float4*)(Bb + (size_t)b_r1 * N + b_c0);
    #pragma unroll
    for (int u = 0; u < 4; u++) {
        float av0 = (u==0)?a_st0.x:(u==1)?a_st0.y:(u==2)?a_st0.z:a_st0.w;
        float av1 = (u==0)?a_st1.x:(u==1)?a_st1.y:(u==2)?a_st1.z:a_st1.w;
        float* p0 = As2 + (a_c0 + u) * AS_STRIDE + 2 * a_r0;
        float* p1 = As2 + (a_c0 + u) * AS_STRIDE + 2 * a_r1;
        p0[0] = av0; p0[1] = av0;
        p1[0] = av1; p1[1] = av1;
    }
    *(float4*)(Bs + b_r0 * 128 + b_c0) = b_st0;
    *(float4*)(Bs + b_r1 * 128 + b_c0) = b_st1;
    __syncthreads();

    const int nt = K >> 4;
    int cur = 0;
    for (int t = 0; t < nt; t++) {
        if (t + 1 < nt) {
            const int k0 = (t + 1) << 4;
            a_st0 = *(const float4*)(Ab + (size_t)a_r0 * K + k0 + a_c0);
            a_st1 = *(const float4*)(Ab + (size_t)a_r1 * K + k0 + a_c0);
            b_st0 = *(const float4*)(Bb + (size_t)(k0 + b_r0) * N + b_c0);
            b_st1 = *(const float4*)(Bb + (size_t)(k0 + b_r1) * N + b_c0);
        }

        const float* Ac = As2 + cur * AS_BUF + ty * 16;
        const float* Bc = Bs  + cur * BS_BUF + tx * 8;
        #pragma unroll
        for (int kk = 0; kk < 16; kk++) {
            const ulonglong2* pa = (const ulonglong2*)(Ac + kk * AS_STRIDE);
            const ulonglong2* pb = (const ulonglong2*)(Bc + kk * 128);
            ulonglong2 A01 = pa[0], A23 = pa[1], A45 = pa[2], A67 = pa[3];
            ulonglong2 B01 = pb[0], B23 = pb[1];
            ffma2(acc2[0][0], A01.x, B01.x); ffma2(acc2[0][1], A01.x, B01.y);
            ffma2(acc2[0][2], A01.x, B23.x); ffma2(acc2[0][3], A01.x, B23.y);
            ffma2(acc2[1][0], A01.y, B01.x); ffma2(acc2[1][1], A01.y, B01.y);
            ffma2(acc2[1][2], A01.y, B23.x); ffma2(acc2[1][3], A01.y, B23.y);
            ffma2(acc2[2][0], A23.x, B01.x); ffma2(acc2[2][1], A23.x, B01.y);
            ffma2(acc2[2][2], A23.x, B23.x); ffma2(acc2[2][3], A23.x, B23.y);
            ffma2(acc2[3][0], A23.y, B01.x); ffma2(acc2[3][1], A23.y, B01.y);
            ffma2(acc2[3][2], A23.y, B23.x); ffma2(acc2[3][3], A23.y, B23.y);
            ffma2(acc2[4][0], A45.x, B01.x); ffma2(acc2[4][1], A45.x, B01.y);
            ffma2(acc2[4][2], A45.x, B23.x); ffma2(acc2[4][3], A45.x, B23.y);
            ffma2(acc2[5][0], A45.y, B01.x); ffma2(acc2[5][1], A45.y, B01.y);
            ffma2(acc2[5][2], A45.y, B23.x); ffma2(acc2[5][3], A45.y, B23.y);
            ffma2(acc2[6][0], A67.x, B01.x); ffma2(acc2[6][1], A67.x, B01.y);
            ffma2(acc2[6][2], A67.x, B23.x); ffma2(acc2[6][3], A67.x, B23.y);
            ffma2(acc2[7][0], A67.y, B01.x); ffma2(acc2[7][1], A67.y, B01.y);
            ffma2(acc2[7][2], A67.y, B23.x); ffma2(acc2[7][3], A67.y, B23.y);
        }

        if (t + 1 < nt) {
            const int nxt = cur ^ 1;
            float* Asn = As2 + nxt * AS_BUF;
            float* Bsn = Bs  + nxt * BS_BUF;
            #pragma unroll
            for (int u = 0; u < 4; u++) {
                float av0 = (u==0)?a_st0.x:(u==1)?a_st0.y:(u==2)?a_st0.z:a_st0.w;
                float av1 = (u==0)?a_st1.x:(u==1)?a_st1.y:(u==2)?a_st1.z:a_st1.w;
                float* p0 = Asn + (a_c0 + u) * AS_STRIDE + 2 * a_r0;
                float* p1 = Asn + (a_c0 + u) * AS_STRIDE + 2 * a_r1;
                p0[0] = av0; p0[1] = av0;
                p1[0] = av1; p1[1] = av1;
            }
            *(float4*)(Bsn + b_r0 * 128 + b_c0) = b_st0;
            *(float4*)(Bsn + b_r1 * 128 + b_c0) = b_st1;
            __syncthreads();
            cur = nxt;
        }
    }

    // epilogue
    const int colb = bn * 128 + tx * 8;
    float badd[8];
    if (bias) {
        float4 bb0 = *(const float4*)(bias + colb);
        float4 bb1 = *(const float4*)(bias + colb + 4);
        badd[0]=bb0.x; badd[1]=bb0.y; badd[2]=bb0.z; badd[3]=bb0.w;
        badd[4]=bb1.x; badd[5]=bb1.y; badd[6]=bb1.z; badd[7]=bb1.w;
    } else {
        #pragma unroll
        for (int j = 0; j < 8; j++) badd[j] = 0.f;
    }

    #pragma unroll
    for (int i = 0; i < 8; i++) {
        const size_t row = (size_t)bm * 128 + ty * 8 + i;
        float vv[8];
        float2 p0 = unpk2(acc2[i][0]), p1 = unpk2(acc2[i][1]);
        float2 p2 = unpk2(acc2[i][2]), p3 = unpk2(acc2[i][3]);
        vv[0]=p0.x+badd[0]; vv[1]=p0.y+badd[1]; vv[2]=p1.x+badd[2]; vv[3]=p1.y+badd[3];
        vv[4]=p2.x+badd[4]; vv[5]=p2.y+badd[5]; vv[6]=p3.x+badd[6]; vv[7]=p3.y+badd[7];
        if (resid) {
            float4 r0 = *(const float4*)(resid + row * N + colb);
            float4 r1 = *(const float4*)(resid + row * N + colb + 4);
            vv[0]+=r0.x; vv[1]+=r0.y; vv[2]+=r0.z; vv[3]+=r0.w;
            vv[4]+=r1.x; vv[5]+=r1.y; vv[6]+=r1.z; vv[7]+=r1.w;
        }
        if (do_relu) {
            #pragma unroll
            for (int j = 0; j < 8; j++) vv[j] = fmaxf(vv[j], 0.f);
        }
        *(float4*)(Cmat + row * N + colb)     = make_float4(vv[0], vv[1], vv[2], vv[3]);
        *(float4*)(Cmat + row * N + colb + 4) = make_float4(vv[4], vv[5], vv[6], vv[7]);
    }
}

// Generic single-GEMM wrapper
__global__ __launch_bounds__(256) void sgemm_kernel(
    const float* __restrict__ A, const float* __restrict__ B,
    const float* __restrict__ bias, const float* __restrict__ resid,
    float* __restrict__ Cmat, int N, int K, int do_relu)
{
    extern __shared__ float sm[];
    sgemm_core(A, B, bias, resid, Cmat, N, K, do_relu,
               blockIdx.y, blockIdx.x, sm);
}

// Fused QKV: gridDim.x = 24 (3 matrices x 8 column tiles)
__global__ __launch_bounds__(256) void qkv_kernel(
    const float* __restrict__ A,
    const float* __restrict__ Wq, const float* __restrict__ Wk,
    const float* __restrict__ Wv,
    float* __restrict__ Oq, float* __restrict__ Ok, float* __restrict__ Ov)
{
    extern __shared__ float sm[];
    const int mat = blockIdx.x >> 3;
    const int bn  = blockIdx.x & 7;
    const float* B = (mat == 0) ? Wq : (mat == 1) ? Wk : Wv;
    float*       C = (mat == 0) ? Oq : (mat == 1) ? Ok : Ov;
    sgemm_core(A, B, nullptr, nullptr, C, CC, CC, 0, blockIdx.y, bn, sm);
}

// ---------------------------------------------------------------------------
// Flash-attention (causal), fp32 SIMT.
// One block per (b, h, 64-row q tile). Q/K/V live in [B,T,C] layout.
// 256 threads as 16x16; each thread owns a 4x4 micro-tile.
// smem: Qs[64][64], KPs[64][65] (K tile reused for P), Vs[64][64] = 49408 B.
// KPs row stride is odd -> scalar access only.
// ---------------------------------------------------------------------------
__global__ __launch_bounds__(256) void attn_kernel(
    const float* __restrict__ Q, const float* __restrict__ K,
    const float* __restrict__ V, float* __restrict__ O)
{
    extern __shared__ float sm[];
    float* Qs  = sm;            // 64*64
    float* KPs = sm + 4096;     // 64*65
    float* Vs  = KPs + 4160;    // 64*64

    const int tid = threadIdx.x;
    const int tx = tid & 15, ty = tid >> 4;
    const int qb = blockIdx.x, h = blockIdx.y, b = blockIdx.z;

    const size_t base = (size_t)b * TT * CC + (size_t)h * HDD;
    const float* Qb = Q + base;
    const float* Kb = K + base;
    const float* Vb = V + base;

    for (int s = tid; s < 64 * 16; s += 256) {
        int r = s >> 4, c4 = (s & 15) << 2;
        *(float4*)(Qs + r * 64 + c4) =
            *(const float4*)(Qb + (size_t)(qb * 64 + r) * CC + c4);
    }

    float m_i[4], l_i[4], oacc[4][4];
    #pragma unroll
    for (int i = 0; i < 4; i++) {
        m_i[i] = -1e30f; l_i[i] = 0.f;
        #pragma unroll
        for (int j = 0; j < 4; j++) oacc[i][j] = 0.f;
    }

    for (int kb = 0; kb <= qb; kb++) {
        __syncthreads();
        for (int s = tid; s < 64 * 16; s += 256) {
            int r = s >> 4, c4 = (s & 15) << 2;
            float4 kv4 = *(const float4*)(Kb + (size_t)(kb * 64 + r) * CC + c4);
            float* kp = KPs + r * 65 + c4;
            kp[0] = kv4.x; kp[1] = kv4.y; kp[2] = kv4.z; kp[3] = kv4.w;
            *(float4*)(Vs + r * 64 + c4) =
                *(const float4*)(Vb + (size_t)(kb * 64 + r) * CC + c4);
        }
        __syncthreads();

        float sv[4][4];
        #pragma unroll
        for (int i = 0; i < 4; i++)
            #pragma unroll
            for (int j = 0; j < 4; j++) sv[i][j] = 0.f;

        for (int d = 0; d < 64; d++) {
            float qr[4], kr[4];
            #pragma unroll
            for (int i = 0; i < 4; i++) qr[i] = Qs[(ty * 4 + i) * 64 + d];
            #pragma unroll
            for (int j = 0; j < 4; j++) kr[j] = KPs[(tx * 4 + j) * 65 + d];
            #pragma unroll
            for (int i = 0; i < 4; i++)
                #pragma unroll
                for (int j = 0; j < 4; j++) sv[i][j] += qr[i] * kr[j];
        }

        const float scale = 0.125f;
        const int qrow0 = qb * 64 + ty * 4;
        const int kcol0 = kb * 64 + tx * 4;
        const bool diag = (kb == qb);
        #pragma unroll
        for (int i = 0; i < 4; i++)
            #pragma unroll
            for (int j = 0; j < 4; j++) {
                float val = sv[i][j] * scale;
                if (diag && (kcol0 + j > qrow0 + i)) val = -1e30f;
                sv[i][j] = val;
            }

        #pragma unroll
        for (int i = 0; i < 4; i++) {
            float rm = fmaxf(fmaxf(sv[i][0], sv[i][1]), fmaxf(sv[i][2], sv[i][3]));
            #pragma unroll
            for (int msk = 1; msk < 16; msk <<= 1)
                rm = fmaxf(rm, __shfl_xor_sync(0xffffffffu, rm, msk));
            const float mnew = fmaxf(m_i[i], rm);
            const float alpha = __expf(m_i[i] - mnew);
            l_i[i] *= alpha;
            #pragma unroll
            for (int j = 0; j < 4; j++) oacc[i][j] *= alpha;
            float rs = 0.f;
            #pragma unroll
            for (int j = 0; j < 4; j++) {
                sv[i][j] = __expf(sv[i][j] - mnew);
                rs += sv[i][j];
            }
            #pragma unroll
            for (int msk = 1; msk < 16; msk <<= 1)
                rs += __shfl_xor_sync(0xffffffffu, rs, msk);
            l_i[i] += rs;
            m_i[i] = mnew;
        }

        __syncthreads();
        #pragma unroll
        for (int i = 0; i < 4; i++)
            #pragma unroll
            for (int j = 0; j < 4; j++)
                KPs[(ty * 4 + i) * 65 + tx * 4 + j] = sv[i][j];
        __syncthreads();

        for (int d = 0; d < 64; d++) {
            float pr[4], vr[4];
            #pragma unroll
            for (int i = 0; i < 4; i++) pr[i] = KPs[(ty * 4 + i) * 65 + d];
            #pragma unroll
            for (int j = 0; j < 4; j++) vr[j] = Vs[d * 64 + tx * 4 + j];
            #pragma unroll
            for (int i = 0; i < 4; i++)
                #pragma unroll
                for (int j = 0; j < 4; j++) oacc[i][j] += pr[i] * vr[j];
        }
    }

    float* Ob = O + base;
    #pragma unroll
    for (int i = 0; i < 4; i++) {
        const float inv = 1.0f / l_i[i];
        float4 ov = make_float4(oacc[i][0] * inv, oacc[i][1] * inv,
                                oacc[i][2] * inv, oacc[i][3] * inv);
        *(float4*)(Ob + (size_t)(qb * 64 + ty * 4 + i) * CC + tx * 4) = ov;
    }
}

// ---------------------------------------------------------------------------
// Launch
// ---------------------------------------------------------------------------
extern "C" void kernel_launch(void* const* d_in, const int* in_sizes, int n_in,
                              void* d_out, int out_size)
{
    const float* x     = (const float*)d_in[0];
    const float* ln1_w = (const float*)d_in[1];
    const float* ln1_b = (const float*)d_in[2];
    const float* Wq    = (const float*)d_in[3];
    const float* Wk    = (const float*)d_in[4];
    const float* Wv    = (const float*)d_in[5];
    const float* Wp    = (const float*)d_in[6];
    const float* bp    = (const float*)d_in[7];
    const float* ln2_w = (const float*)d_in[8];
    const float* ln2_b = (const float*)d_in[9];
    const float* W1    = (const float*)d_in[10];
    const float* b1    = (const float*)d_in[11];
    const float* W2    = (const float*)d_in[12];
    const float* b2    = (const float*)d_in[13];

    float *h, *q, *k, *v, *o, *x1, *h2, *ff;
    cudaGetSymbolAddress((void**)&h,  g_h);
    cudaGetSymbolAddress((void**)&q,  g_q);
    cudaGetSymbolAddress((void**)&k,  g_k);
    cudaGetSymbolAddress((void**)&v,  g_v);
    cudaGetSymbolAddress((void**)&o,  g_o);
    cudaGetSymbolAddress((void**)&x1, g_x1);
    cudaGetSymbolAddress((void**)&h2, g_h2);
    cudaGetSymbolAddress((void**)&ff, g_ff);

    cudaFuncSetAttribute(sgemm_kernel,
                         cudaFuncAttributeMaxDynamicSharedMemorySize, SGEMM_SMEM);
    cudaFuncSetAttribute(qkv_kernel,
                         cudaFuncAttributeMaxDynamicSharedMemorySize, SGEMM_SMEM);

    // 1. h = LN1(x)
    ln_kernel<<<MM, 256>>>(x, ln1_w, ln1_b, h);

    // 2. q/k/v = h @ W{q,k,v} in ONE launch
    dim3 gQKV3(24, MM / 128);
    qkv_kernel<<<gQKV3, 256, SGEMM_SMEM>>>(h, Wq, Wk, Wv, q, k, v);

    // 3. o = causal_attention(q, k, v)
    const size_t attn_smem = (4096 + 4160 + 4096) * sizeof(float);  // 49408
    cudaFuncSetAttribute(attn_kernel,
                         cudaFuncAttributeMaxDynamicSharedMemorySize,
                         (int)attn_smem);
    dim3 gA(TT / 64, NHH, BB);
    attn_kernel<<<gA, 256, attn_smem>>>(q, k, v, o);

    // 4. x1 = x + o @ Wp + bp
    dim3 gProj(CC / 128, MM / 128);
    sgemm_kernel<<<gProj, 256, SGEMM_SMEM>>>(o, Wp, bp, x, x1, CC, CC, 0);

    // 5. h2 = LN2(x1)
    ln_kernel<<<MM, 256>>>(x1, ln2_w, ln2_b, h2);

    // 6. ff = relu(h2 @ W1 + b1)
    dim3 gFF(FFF / 128, MM / 128);
    sgemm_kernel<<<gFF, 256, SGEMM_SMEM>>>(h2, W1, b1, nullptr, ff, FFF, CC, 1);

    // 7. out = x1 + ff @ W2 + b2
    dim3 gOut(CC / 128, MM / 128);
    sgemm_kernel<<<gOut, 256, SGEMM_SMEM>>>(ff, W2, b2, x1, (float*)d_out, CC, FFF, 0);
}

// round 10
// speedup vs baseline: 1.0475x; 1.0475x over previous
#include <cuda_runtime.h>
#include <cuda_bf16.h>
#include <cstddef>

// Problem constants
#define BB 2
#define TT 2048
#define CC 1024
#define NHH 16
#define HDD 64
#define FFF 4096
#define MM (BB*TT)   // 4096

// ---------------------------------------------------------------------------
// Scratch (static device arrays — allocation-free per harness rules)
// ---------------------------------------------------------------------------
__device__ float g_h [MM*CC];   // LN1 output
__device__ float g_q [MM*CC];
__device__ float g_k [MM*CC];
__device__ float g_v [MM*CC];
__device__ float g_o [MM*CC];   // attention output, [B,T,C] layout
__device__ float g_x1[MM*CC];   // x + attn proj (residual 1)
__device__ float g_h2[MM*CC];   // LN2 output
__device__ float g_ff[MM*FFF];  // relu(h2@W1+b1)

// ---------------------------------------------------------------------------
// Packed fp32x2 helpers. FFMA2 = 4 FLOP/issue at rt_SMSP=2.
// Operand marshalling is done via smem layout (A duplicated in smem, B read
// as u64 pairs) so the inner loop is pure LDS.128 + FFMA2 — no MOVs.
// ---------------------------------------------------------------------------
__device__ __forceinline__ void ffma2(unsigned long long& d,
                                      unsigned long long a,
                                      unsigned long long b) {
    asm("fma.rn.f32x2 %0, %1, %2, %0;" : "+l"(d) : "l"(a), "l"(b));
}
__device__ __forceinline__ float2 unpk2(unsigned long long v) {
    float2 f;
    asm("mov.b64 {%0, %1}, %2;" : "=f"(f.x), "=f"(f.y) : "l"(v));
    return f;
}

// ---------------------------------------------------------------------------
// LayerNorm: one block per row, 256 threads, C=1024 (4 floats / thread)
// ---------------------------------------------------------------------------
__global__ __launch_bounds__(256) void ln_kernel(
    const float* __restrict__ x, const float* __restrict__ w,
    const float* __restrict__ bb, float* __restrict__ out)
{
    const int row = blockIdx.x;
    const int tid = threadIdx.x;
    const float* xr = x + (size_t)row * CC;
    float4 xv = ((const float4*)xr)[tid];

    float s  = xv.x + xv.y + xv.z + xv.w;
    float sq = xv.x*xv.x + xv.y*xv.y + xv.z*xv.z + xv.w*xv.w;

    #pragma unroll
    for (int m = 16; m > 0; m >>= 1) {
        s  += __shfl_xor_sync(0xffffffffu, s,  m);
        sq += __shfl_xor_sync(0xffffffffu, sq, m);
    }
    __shared__ float ss[8], ssq[8];
    const int lane = tid & 31, wid = tid >> 5;
    if (lane == 0) { ss[wid] = s; ssq[wid] = sq; }
    __syncthreads();
    float ts = 0.f, tsq = 0.f;
    #pragma unroll
    for (int i = 0; i < 8; i++) { ts += ss[i]; tsq += ssq[i]; }

    const float mu  = ts * (1.0f / CC);
    const float var = tsq * (1.0f / CC) - mu * mu;
    const float rs  = rsqrtf(var + 1e-5f);

    float4 wv = ((const float4*)w)[tid];
    float4 bv = ((const float4*)bb)[tid];
    float4 ov;
    ov.x = (xv.x - mu) * rs * wv.x + bv.x;
    ov.y = (xv.y - mu) * rs * wv.y + bv.y;
    ov.z = (xv.z - mu) * rs * wv.z + bv.z;
    ov.w = (xv.w - mu) * rs * wv.w + bv.w;
    ((float4*)(out + (size_t)row * CC))[tid] = ov;
}

// ---------------------------------------------------------------------------
// SGEMM core: C[M,N] = A[M,K] @ B[K,N] (+bias) (+resid) (relu?)
// 128x128 tile, BK=16, 8x8 per thread as 8x4 f32x2 pairs, 256 threads.
// Smem: As2 = A transposed AND duplicated along M (As2[kk][2m]=As2[kk][2m+1]
//       =A[m][kk]) so LDS.128 yields FFMA2-ready duplicated pairs
//       (ty-indexed -> warp-broadcast, crossbar-cheap).
//       Bs read as ulonglong2 -> natural f32x2 pairs. Inner loop: 6 LDS + 32 FFMA2.
// Dynamic smem: 2*16*264 + 2*16*128 floats = 50176 bytes, double buffered.
// __launch_bounds__(256,2) on callers caps regs at 128 -> 2 CTAs/SM.
// ---------------------------------------------------------------------------
#define AS_STRIDE 264          // 256 duplicated floats + 8 pad
#define AS_BUF    (16 * AS_STRIDE)
#define BS_BUF    (16 * 128)
#define SGEMM_SMEM ((2 * AS_BUF + 2 * BS_BUF) * 4)   // 50176 bytes

__device__ __forceinline__ void sgemm_core(
    const float* __restrict__ A, const float* __restrict__ B,
    const float* __restrict__ bias, const float* __restrict__ resid,
    float* __restrict__ Cmat, int N, int K, int do_relu,
    int bm, int bn, float* sm)
{
    float* As2 = sm;                 // [2][16][264]
    float* Bs  = sm + 2 * AS_BUF;    // [2][16][128]

    const int tid = threadIdx.x;
    const int tx = tid & 15;
    const int ty = tid >> 4;

    const float* Ab = A + (size_t)bm * 128 * K;
    const float* Bb = B + (size_t)bn * 128;

    const int a_r0 = tid >> 2,           a_c0 = (tid & 3) << 2;
    const int a_r1 = a_r0 + 64;
    const int b_r0 = tid >> 5,           b_c0 = (tid & 31) << 2;
    const int b_r1 = b_r0 + 8;

    unsigned long long acc2[8][4];
    #pragma unroll
    for (int i = 0; i < 8; i++)
        #pragma unroll
        for (int j = 0; j < 4; j++) acc2[i][j] = 0ull;

    float4 a_st0, a_st1, b_st0, b_st1;

    // prologue: tile 0 -> buffer 0
    a_st0 = *(const float4*)(Ab + (size_t)a_r0 * K + a_c0);
    a_st1 = *(const float4*)(Ab + (size_t)a_r1 * K + a_c0);
    b_st0 = *(const float4*)(Bb + (size_t)b_r0 * N + b_c0);
    b_st1 = *(const float4*)(Bb + (size_t)b_r1 * N + b_c0);
    #pragma unroll
    for (int u = 0; u < 4; u++) {
        float av0 = (u==0)?a_st0.x:(u==1)?a_st0.y:(u==2)?a_st0.z:a_st0.w;
        float av1 = (u==0)?a_st1.x:(u==1)?a_st1.y:(u==2)?a_st1.z:a_st1.w;
        float* p0 = As2 + (a_c0 + u) * AS_STRIDE + 2 * a_r0;
        float* p1 = As2 + (a_c0 + u) * AS_STRIDE + 2 * a_r1;
        p0[0] = av0; p0[1] = av0;
        p1[0] = av1; p1[1] = av1;
    }
    *(float4*)(Bs + b_r0 * 128 + b_c0) = b_st0;
    *(float4*)(Bs + b_r1 * 128 + b_c0) = b_st1;
    __syncthreads();

    const int nt = K >> 4;
    int cur = 0;
    for (int t = 0; t < nt; t++) {
        if (t + 1 < nt) {
            const int k0 = (t + 1) << 4;
            a_st0 = *(const float4*)(Ab + (size_t)a_r0 * K + k0 + a_c0);
            a_st1 = *(const float4*)(Ab + (size_t)a_r1 * K + k0 + a_c0);
            b_st0 = *(const float4*)(Bb + (size_t)(k0 + b_r0) * N + b_c0);
            b_st1 = *(const float4*)(Bb + (size_t)(k0 + b_r1) * N + b_c0);
        }

        const float* Ac = As2 + cur * AS_BUF + ty * 16;
        const float* Bc = Bs  + cur * BS_BUF + tx * 8;
        #pragma unroll
        for (int kk = 0; kk < 16; kk++) {
            const ulonglong2* pa = (const ulonglong2*)(Ac + kk * AS_STRIDE);
            const ulonglong2* pb = (const ulonglong2*)(Bc + kk * 128);
            ulonglong2 A01 = pa[0], A23 = pa[1], A45 = pa[2], A67 = pa[3];
            ulonglong2 B01 = pb[0], B23 = pb[1];
            ffma2(acc2[0][0], A01.x, B01.x); ffma2(acc2[0][1], A01.x, B01.y);
            ffma2(acc2[0][2], A01.x, B23.x); ffma2(acc2[0][3], A01.x, B23.y);
            ffma2(acc2[1][0], A01.y, B01.x); ffma2(acc2[1][1], A01.y, B01.y);
            ffma2(acc2[1][2], A01.y, B23.x); ffma2(acc2[1][3], A01.y, B23.y);
            ffma2(acc2[2][0], A23.x, B01.x); ffma2(acc2[2][1], A23.x, B01.y);
            ffma2(acc2[2][2], A23.x, B23.x); ffma2(acc2[2][3], A23.x, B23.y);
            ffma2(acc2[3][0], A23.y, B01.x); ffma2(acc2[3][1], A23.y, B01.y);
            ffma2(acc2[3][2], A23.y, B23.x); ffma2(acc2[3][3], A23.y, B23.y);
            ffma2(acc2[4][0], A45.x, B01.x); ffma2(acc2[4][1], A45.x, B01.y);
            ffma2(acc2[4][2], A45.x, B23.x); ffma2(acc2[4][3], A45.x, B23.y);
            ffma2(acc2[5][0], A45.y, B01.x); ffma2(acc2[5][1], A45.y, B01.y);
            ffma2(acc2[5][2], A45.y, B23.x); ffma2(acc2[5][3], A45.y, B23.y);
            ffma2(acc2[6][0], A67.x, B01.x); ffma2(acc2[6][1], A67.x, B01.y);
            ffma2(acc2[6][2], A67.x, B23.x); ffma2(acc2[6][3], A67.x, B23.y);
            ffma2(acc2[7][0], A67.y, B01.x); ffma2(acc2[7][1], A67.y, B01.y);
            ffma2(acc2[7][2], A67.y, B23.x); ffma2(acc2[7][3], A67.y, B23.y);
        }

        if (t + 1 < nt) {
            const int nxt = cur ^ 1;
            float* Asn = As2 + nxt * AS_BUF;
            float* Bsn = Bs  + nxt * BS_BUF;
            #pragma unroll
            for (int u = 0; u < 4; u++) {
                float av0 = (u==0)?a_st0.x:(u==1)?a_st0.y:(u==2)?a_st0.z:a_st0.w;
                float av1 = (u==0)?a_st1.x:(u==1)?a_st1.y:(u==2)?a_st1.z:a_st1.w;
                float* p0 = Asn + (a_c0 + u) * AS_STRIDE + 2 * a_r0;
                float* p1 = Asn + (a_c0 + u) * AS_STRIDE + 2 * a_r1;
                p0[0] = av0; p0[1] = av0;
                p1[0] = av1; p1[1] = av1;
            }
            *(float4*)(Bsn + b_r0 * 128 + b_c0) = b_st0;
            *(float4*)(Bsn + b_r1 * 128 + b_c0) = b_st1;
            __syncthreads();
            cur = nxt;
        }
    }

    // epilogue
    const int colb = bn * 128 + tx * 8;
    float badd[8];
    if (bias) {
        float4 bb0 = *(const float4*)(bias + colb);
        float4 bb1 = *(const float4*)(bias + colb + 4);
        badd[0]=bb0.x; badd[1]=bb0.y; badd[2]=bb0.z; badd[3]=bb0.w;
        badd[4]=bb1.x; badd[5]=bb1.y; badd[6]=bb1.z; badd[7]=bb1.w;
    } else {
        #pragma unroll
        for (int j = 0; j < 8; j++) badd[j] = 0.f;
    }

    #pragma unroll
    for (int i = 0; i < 8; i++) {
        const size_t row = (size_t)bm * 128 + ty * 8 + i;
        float vv[8];
        float2 p0 = unpk2(acc2[i][0]), p1 = unpk2(acc2[i][1]);
        float2 p2 = unpk2(acc2[i][2]), p3 = unpk2(acc2[i][3]);
        vv[0]=p0.x+badd[0]; vv[1]=p0.y+badd[1]; vv[2]=p1.x+badd[2]; vv[3]=p1.y+badd[3];
        vv[4]=p2.x+badd[4]; vv[5]=p2.y+badd[5]; vv[6]=p3.x+badd[6]; vv[7]=p3.y+badd[7];
        if (resid) {
            float4 r0 = *(const float4*)(resid + row * N + colb);
            float4 r1 = *(const float4*)(resid + row * N + colb + 4);
            vv[0]+=r0.x; vv[1]+=r0.y; vv[2]+=r0.z; vv[3]+=r0.w;
            vv[4]+=r1.x; vv[5]+=r1.y; vv[6]+=r1.z; vv[7]+=r1.w;
        }
        if (do_relu) {
            #pragma unroll
            for (int j = 0; j < 8; j++) vv[j] = fmaxf(vv[j], 0.f);
        }
        *(float4*)(Cmat + row * N + colb)     = make_float4(vv[0], vv[1], vv[2], vv[3]);
        *(float4*)(Cmat + row * N + colb + 4) = make_float4(vv[4], vv[5], vv[6], vv[7]);
    }
}

// Generic single-GEMM wrapper — minBlocks=2 caps regs at 128 (2 CTAs/SM)
__global__ __launch_bounds__(256, 2) void sgemm_kernel(
    const float* __restrict__ A, const float* __restrict__ B,
    const float* __restrict__ bias, const float* __restrict__ resid,
    float* __restrict__ Cmat, int N, int K, int do_relu)
{
    extern __shared__ float sm[];
    sgemm_core(A, B, bias, resid, Cmat, N, K, do_relu,
               blockIdx.y, blockIdx.x, sm);
}

// Fused QKV: gridDim.x = 24 (3 matrices x 8 column tiles)
__global__ __launch_bounds__(256, 2) void qkv_kernel(
    const float* __restrict__ A,
    const float* __restrict__ Wq, const float* __restrict__ Wk,
    const float* __restrict__ Wv,
    float* __restrict__ Oq, float* __restrict__ Ok, float* __restrict__ Ov)
{
    extern __shared__ float sm[];
    const int mat = blockIdx.x >> 3;
    const int bn  = blockIdx.x & 7;
    const float* B = (mat == 0) ? Wq : (mat == 1) ? Wk : Wv;
    float*       C = (mat == 0) ? Oq : (mat == 1) ? Ok : Ov;
    sgemm_core(A, B, nullptr, nullptr, C, CC, CC, 0, blockIdx.y, bn, sm);
}

// ---------------------------------------------------------------------------
// Flash-attention (causal), fp32 SIMT.
// One block per (b, h, 64-row q tile). Q/K/V live in [B,T,C] layout.
// 256 threads as 16x16; each thread owns a 4x4 micro-tile.
// smem: Qs[64][64], KPs[64][65] (K tile reused for P), Vs[64][64] = 49408 B.
// KPs row stride is odd -> scalar access only.
// ---------------------------------------------------------------------------
__global__ __launch_bounds__(256) void attn_kernel(
    const float* __restrict__ Q, const float* __restrict__ K,
    const float* __restrict__ V, float* __restrict__ O)
{
    extern __shared__ float sm[];
    float* Qs  = sm;            // 64*64
    float* KPs = sm + 4096;     // 64*65
    float* Vs  = KPs + 4160;    // 64*64

    const int tid = threadIdx.x;
    const int tx = tid & 15, ty = tid >> 4;
    const int qb = blockIdx.x, h = blockIdx.y, b = blockIdx.z;

    const size_t base = (size_t)b * TT * CC + (size_t)h * HDD;
    const float* Qb = Q + base;
    const float* Kb = K + base;
    const float* Vb = V + base;

    for (int s = tid; s < 64 * 16; s += 256) {
        int r = s >> 4, c4 = (s & 15) << 2;
        *(float4*)(Qs + r * 64 + c4) =
            *(const float4*)(Qb + (size_t)(qb * 64 + r) * CC + c4);
    }

    float m_i[4], l_i[4], oacc[4][4];
    #pragma unroll
    for (int i = 0; i < 4; i++) {
        m_i[i] = -1e30f; l_i[i] = 0.f;
        #pragma unroll
        for (int j = 0; j < 4; j++) oacc[i][j] = 0.f;
    }

    for (int kb = 0; kb <= qb; kb++) {
        __syncthreads();
        for (int s = tid; s < 64 * 16; s += 256) {
            int r = s >> 4, c4 = (s & 15) << 2;
            float4 kv4 = *(const float4*)(Kb + (size_t)(kb * 64 + r) * CC + c4);
            float* kp = KPs + r * 65 + c4;
            kp[0] = kv4.x; kp[1] = kv4.y; kp[2] = kv4.z; kp[3] = kv4.w;
            *(float4*)(Vs + r * 64 + c4) =
                *(const float4*)(Vb + (size_t)(kb * 64 + r) * CC + c4);
        }
        __syncthreads();

        float sv[4][4];
        #pragma unroll
        for (int i = 0; i < 4; i++)
            #pragma unroll
            for (int j = 0; j < 4; j++) sv[i][j] = 0.f;

        for (int d = 0; d < 64; d++) {
            float qr[4], kr[4];
            #pragma unroll
            for (int i = 0; i < 4; i++) qr[i] = Qs[(ty * 4 + i) * 64 + d];
            #pragma unroll
            for (int j = 0; j < 4; j++) kr[j] = KPs[(tx * 4 + j) * 65 + d];
            #pragma unroll
            for (int i = 0; i < 4; i++)
                #pragma unroll
                for (int j = 0; j < 4; j++) sv[i][j] += qr[i] * kr[j];
        }

        const float scale = 0.125f;
        const int qrow0 = qb * 64 + ty * 4;
        const int kcol0 = kb * 64 + tx * 4;
        const bool diag = (kb == qb);
        #pragma unroll
        for (int i = 0; i < 4; i++)
            #pragma unroll
            for (int j = 0; j < 4; j++) {
                float val = sv[i][j] * scale;
                if (diag && (kcol0 + j > qrow0 + i)) val = -1e30f;
                sv[i][j] = val;
            }

        #pragma unroll
        for (int i = 0; i < 4; i++) {
            float rm = fmaxf(fmaxf(sv[i][0], sv[i][1]), fmaxf(sv[i][2], sv[i][3]));
            #pragma unroll
            for (int msk = 1; msk < 16; msk <<= 1)
                rm = fmaxf(rm, __shfl_xor_sync(0xffffffffu, rm, msk));
            const float mnew = fmaxf(m_i[i], rm);
            const float alpha = __expf(m_i[i] - mnew);
            l_i[i] *= alpha;
            #pragma unroll
            for (int j = 0; j < 4; j++) oacc[i][j] *= alpha;
            float rs = 0.f;
            #pragma unroll
            for (int j = 0; j < 4; j++) {
                sv[i][j] = __expf(sv[i][j] - mnew);
                rs += sv[i][j];
            }
            #pragma unroll
            for (int msk = 1; msk < 16; msk <<= 1)
                rs += __shfl_xor_sync(0xffffffffu, rs, msk);
            l_i[i] += rs;
            m_i[i] = mnew;
        }

        __syncthreads();
        #pragma unroll
        for (int i = 0; i < 4; i++)
            #pragma unroll
            for (int j = 0; j < 4; j++)
                KPs[(ty * 4 + i) * 65 + tx * 4 + j] = sv[i][j];
        __syncthreads();

        for (int d = 0; d < 64; d++) {
            float pr[4], vr[4];
            #pragma unroll
            for (int i = 0; i < 4; i++) pr[i] = KPs[(ty * 4 + i) * 65 + d];
            #pragma unroll
            for (int j = 0; j < 4; j++) vr[j] = Vs[d * 64 + tx * 4 + j];
            #pragma unroll
            for (int i = 0; i < 4; i++)
                #pragma unroll
                for (int j = 0; j < 4; j++) oacc[i][j] += pr[i] * vr[j];
        }
    }

    float* Ob = O + base;
    #pragma unroll
    for (int i = 0; i < 4; i++) {
        const float inv = 1.0f / l_i[i];
        float4 ov = make_float4(oacc[i][0] * inv, oacc[i][1] * inv,
                                oacc[i][2] * inv, oacc[i][3] * inv);
        *(float4*)(Ob + (size_t)(qb * 64 + ty * 4 + i) * CC + tx * 4) = ov;
    }
}

// ---------------------------------------------------------------------------
// Launch
// ---------------------------------------------------------------------------
extern "C" void kernel_launch(void* const* d_in, const int* in_sizes, int n_in,
                              void* d_out, int out_size)
{
    const float* x     = (const float*)d_in[0];
    const float* ln1_w = (const float*)d_in[1];
    const float* ln1_b = (const float*)d_in[2];
    const float* Wq    = (const float*)d_in[3];
    const float* Wk    = (const float*)d_in[4];
    const float* Wv    = (const float*)d_in[5];
    const float* Wp    = (const float*)d_in[6];
    const float* bp    = (const float*)d_in[7];
    const float* ln2_w = (const float*)d_in[8];
    const float* ln2_b = (const float*)d_in[9];
    const float* W1    = (const float*)d_in[10];
    const float* b1    = (const float*)d_in[11];
    const float* W2    = (const float*)d_in[12];
    const float* b2    = (const float*)d_in[13];

    float *h, *q, *k, *v, *o, *x1, *h2, *ff;
    cudaGetSymbolAddress((void**)&h,  g_h);
    cudaGetSymbolAddress((void**)&q,  g_q);
    cudaGetSymbolAddress((void**)&k,  g_k);
    cudaGetSymbolAddress((void**)&v,  g_v);
    cudaGetSymbolAddress((void**)&o,  g_o);
    cudaGetSymbolAddress((void**)&x1, g_x1);
    cudaGetSymbolAddress((void**)&h2, g_h2);
    cudaGetSymbolAddress((void**)&ff, g_ff);

    cudaFuncSetAttribute(sgemm_kernel,
                         cudaFuncAttributeMaxDynamicSharedMemorySize, SGEMM_SMEM);
    cudaFuncSetAttribute(qkv_kernel,
                         cudaFuncAttributeMaxDynamicSharedMemorySize, SGEMM_SMEM);

    // 1. h = LN1(x)
    ln_kernel<<<MM, 256>>>(x, ln1_w, ln1_b, h);

    // 2. q/k/v = h @ W{q,k,v} in ONE launch
    dim3 gQKV3(24, MM / 128);
    qkv_kernel<<<gQKV3, 256, SGEMM_SMEM>>>(h, Wq, Wk, Wv, q, k, v);

    // 3. o = causal_attention(q, k, v)
    const size_t attn_smem = (4096 + 4160 + 4096) * sizeof(float);  // 49408
    cudaFuncSetAttribute(attn_kernel,
                         cudaFuncAttributeMaxDynamicSharedMemorySize,
                         (int)attn_smem);
    dim3 gA(TT / 64, NHH, BB);
    attn_kernel<<<gA, 256, attn_smem>>>(q, k, v, o);

    // 4. x1 = x + o @ Wp + bp
    dim3 gProj(CC / 128, MM / 128);
    sgemm_kernel<<<gProj, 256, SGEMM_SMEM>>>(o, Wp, bp, x, x1, CC, CC, 0);

    // 5. h2 = LN2(x1)
    ln_kernel<<<MM, 256>>>(x1, ln2_w, ln2_b, h2);

    // 6. ff = relu(h2 @ W1 + b1)
    dim3 gFF(FFF / 128, MM / 128);
    sgemm_kernel<<<gFF, 256, SGEMM_SMEM>>>(h2, W1, b1, nullptr, ff, FFF, CC, 1);

    // 7. out = x1 + ff @ W2 + b2
    dim3 gOut(CC / 128, MM / 128);
    sgemm_kernel<<<gOut, 256, SGEMM_SMEM>>>(ff, W2, b2, x1, (float*)d_out, CC, FFF, 0);
}

// round 13
// speedup vs baseline: 2.1027x; 2.0073x over previous
#include <cuda_runtime.h>
#include <cuda_bf16.h>
#include <cstddef>

// Problem constants
#define BB 2
#define TT 2048
#define CC 1024
#define NHH 16
#define HDD 64
#define FFF 4096
#define MM (BB*TT)   // 4096

// ---------------------------------------------------------------------------
// Scratch (static device arrays — allocation-free per harness rules)
// ---------------------------------------------------------------------------
__device__ float g_q [MM*CC];
__device__ float g_k [MM*CC];
__device__ float g_v [MM*CC];
__device__ float g_o [MM*CC];
__device__ float g_x1[MM*CC];
__device__ float g_ff[MM*FFF];

// Activation bf16 split buffers (reused for h, o, h2, ff sequentially)
__device__ __nv_bfloat16 g_ah[MM*FFF];
__device__ __nv_bfloat16 g_al[MM*FFF];

// Weight bf16 split, TRANSPOSED to [N,K] K-major
__device__ __nv_bfloat16 g_wqh[CC*CC],  g_wql[CC*CC];
__device__ __nv_bfloat16 g_wkh[CC*CC],  g_wkl[CC*CC];
__device__ __nv_bfloat16 g_wvh[CC*CC],  g_wvl[CC*CC];
__device__ __nv_bfloat16 g_wph[CC*CC],  g_wpl[CC*CC];
__device__ __nv_bfloat16 g_w1h[FFF*CC], g_w1l[FFF*CC];
__device__ __nv_bfloat16 g_w2h[CC*FFF], g_w2l[CC*FFF];

// ---------------------------------------------------------------------------
// HMMA helpers (sm_80-era PTX; legal on plain sm_103 target)
// ---------------------------------------------------------------------------
__device__ __forceinline__ unsigned smem_u32(const void* p) {
    unsigned a;
    asm("{ .reg .u64 t; cvta.to.shared.u64 t, %1; cvt.u32.u64 %0, t; }"
        : "=r"(a) : "l"(p));
    return a;
}
__device__ __forceinline__ void ldm_x4(unsigned* r, unsigned addr) {
    asm volatile("ldmatrix.sync.aligned.m8n8.x4.shared.b16 {%0,%1,%2,%3}, [%4];"
        : "=r"(r[0]), "=r"(r[1]), "=r"(r[2]), "=r"(r[3]) : "r"(addr));
}
__device__ __forceinline__ void mma_bf16(float* d, const unsigned* a,
                                         const unsigned* b) {
    asm volatile(
        "mma.sync.aligned.m16n8k16.row.col.f32.bf16.bf16.f32 "
        "{%0,%1,%2,%3}, {%4,%5,%6,%7}, {%8,%9}, {%0,%1,%2,%3};"
        : "+f"(d[0]), "+f"(d[1]), "+f"(d[2]), "+f"(d[3])
        : "r"(a[0]), "r"(a[1]), "r"(a[2]), "r"(a[3]), "r"(b[0]), "r"(b[1]));
}

// ---------------------------------------------------------------------------
// HMMA GEMM: out[M,N] = split_A[M,K] @ split_B[N,K]^T (+bias)(+resid)(relu)
// 128x128 CTA tile, BK=32, 8 warps (32m x 64n each), bf16x3 split passes.
// Smem tiles: 128 rows x 32 bf16, row stride 40 bf16 (80 B) -> the 8
// ldmatrix row addrs land on distinct 16B slots mod 128B: conflict-free.
// Double-buffered with register prefetch (proven R6 pattern).
// ---------------------------------------------------------------------------
#define TSB 40                         // tile row stride in bf16
#define TILE_B (128 * TSB * 2)         // 10240 bytes per tile
#define BUF_B  (4 * TILE_B)            // Ah, Al, Bh, Bl
#define HM_SMEM (2 * BUF_B)            // 81920 bytes

__device__ __forceinline__ void hm_store(
    char* buf, const uint4* va, int tid)
{
    #pragma unroll
    for (int it = 0; it < 2; it++) {
        const int idx = tid + it * 256;          // 0..511
        const int r   = idx >> 2;                // 0..127
        const int c8  = (idx & 3) << 3;          // 0,8,16,24
        const int off = (r * TSB + c8) * 2;      // bytes; 16B aligned
        *(uint4*)(buf + off)              = va[it];
        *(uint4*)(buf + TILE_B + off)     = va[2 + it];
        *(uint4*)(buf + 2 * TILE_B + off) = va[4 + it];
        *(uint4*)(buf + 3 * TILE_B + off) = va[6 + it];
    }
}

__device__ __forceinline__ void hm_ldg(
    uint4* va, int k0,
    const __nv_bfloat16* __restrict__ Ah, const __nv_bfloat16* __restrict__ Al,
    int arow0,
    const __nv_bfloat16* __restrict__ Bh, const __nv_bfloat16* __restrict__ Bl,
    int brow0, int K, int tid)
{
    #pragma unroll
    for (int it = 0; it < 2; it++) {
        const int idx = tid + it * 256;
        const int r   = idx >> 2;
        const int c8  = (idx & 3) << 3;
        const size_t ga = (size_t)(arow0 + r) * K + k0 + c8;
        const size_t gb = (size_t)(brow0 + r) * K + k0 + c8;
        va[it]     = *(const uint4*)(Ah + ga);
        va[2 + it] = *(const uint4*)(Al + ga);
        va[4 + it] = *(const uint4*)(Bh + gb);
        va[6 + it] = *(const uint4*)(Bl + gb);
    }
}

__device__ void hm_core(
    const __nv_bfloat16* __restrict__ Ah, const __nv_bfloat16* __restrict__ Al,
    const __nv_bfloat16* __restrict__ Bh, const __nv_bfloat16* __restrict__ Bl,
    const float* __restrict__ bias, const float* __restrict__ resid,
    float* __restrict__ out, int N, int K, int relu, int bm, int bn, char* sm)
{
    const int tid  = threadIdx.x;
    const int wid  = tid >> 5, lane = tid & 31;
    const int wm   = wid & 3;              // m group (4 x 32 rows)
    const int wn   = wid >> 2;             // n group (2 x 64 cols)
    const unsigned sbase = smem_u32(sm);
    const int arow0 = bm * 128, brow0 = bn * 128;

    float acc[2][8][4];
    #pragma unroll
    for (int i = 0; i < 2; i++)
        #pragma unroll
        for (int j = 0; j < 8; j++)
            #pragma unroll
            for (int c = 0; c < 4; c++) acc[i][j][c] = 0.f;

    uint4 va[8];
    hm_ldg(va, 0, Ah, Al, arow0, Bh, Bl, brow0, K, tid);
    hm_store(sm, va, tid);
    __syncthreads();

    // ldmatrix lane-address components
    const int l8 = lane & 7, q = lane >> 3;
    const int amr = (q & 1) * 8 + l8;      // A: row within 16, k-half = q>>1
    const int akc = (q >> 1) * 8;
    const int bnr = (q >> 1) * 8 + l8;     // B: n within 16, k-half = q&1
    const int bkc = (q & 1) * 8;

    const int nt_chunks = K >> 5;
    int cur = 0;
    for (int t = 0; t < nt_chunks; t++) {
        if (t + 1 < nt_chunks)
            hm_ldg(va, (t + 1) << 5, Ah, Al, arow0, Bh, Bl, brow0, K, tid);

        const unsigned ab  = sbase + cur * BUF_B;
        const unsigned alb = ab + TILE_B;
        const unsigned bhb = ab + 2 * TILE_B;
        const unsigned blb = ab + 3 * TILE_B;

        #pragma unroll
        for (int ks = 0; ks < 2; ks++) {
            unsigned Afh[2][4], Afl[2][4];
            #pragma unroll
            for (int mt = 0; mt < 2; mt++) {
                const int row = wm * 32 + mt * 16 + amr;
                const int off = (row * TSB + ks * 16 + akc) * 2;
                ldm_x4(Afh[mt], ab  + off);
                ldm_x4(Afl[mt], alb + off);
            }
            #pragma unroll
            for (int np = 0; np < 4; np++) {
                const int nrow = wn * 64 + np * 16 + bnr;
                const int off  = (nrow * TSB + ks * 16 + bkc) * 2;
                unsigned Bfh[4], Bfl[4];
                ldm_x4(Bfh, bhb + off);
                ldm_x4(Bfl, blb + off);
                #pragma unroll
                for (int mt = 0; mt < 2; mt++) {
                    mma_bf16(acc[mt][np*2],   Afh[mt], Bfh);
                    mma_bf16(acc[mt][np*2+1], Afh[mt], Bfh + 2);
                    mma_bf16(acc[mt][np*2],   Afh[mt], Bfl);
                    mma_bf16(acc[mt][np*2+1], Afh[mt], Bfl + 2);
                    mma_bf16(acc[mt][np*2],   Afl[mt], Bfh);
                    mma_bf16(acc[mt][np*2+1], Afl[mt], Bfh + 2);
                }
            }
        }

        if (t + 1 < nt_chunks) {
            const int nxt = cur ^ 1;
            hm_store(sm + nxt * BUF_B, va, tid);
            __syncthreads();
            cur = nxt;
        }
    }

    // epilogue: write fragments straight to gmem
    const int colb = bn * 128 + wn * 64;
    #pragma unroll
    for (int mt = 0; mt < 2; mt++) {
        const int r0 = arow0 + wm * 32 + mt * 16 + (lane >> 2);
        #pragma unroll
        for (int nt = 0; nt < 8; nt++) {
            const int c0 = colb + nt * 8 + (lane & 3) * 2;
            float* cc = acc[mt][nt];
            float v0 = cc[0], v1 = cc[1], v2 = cc[2], v3 = cc[3];
            if (bias) {
                const float b0 = bias[c0], b1 = bias[c0 + 1];
                v0 += b0; v1 += b1; v2 += b0; v3 += b1;
            }
            if (resid) {
                const float2 ra = *(const float2*)(resid + (size_t)r0 * N + c0);
                const float2 rb = *(const float2*)(resid + (size_t)(r0+8) * N + c0);
                v0 += ra.x; v1 += ra.y; v2 += rb.x; v3 += rb.y;
            }
            if (relu) {
                v0 = fmaxf(v0, 0.f); v1 = fmaxf(v1, 0.f);
                v2 = fmaxf(v2, 0.f); v3 = fmaxf(v3, 0.f);
            }
            *(float2*)(out + (size_t)r0 * N + c0)       = make_float2(v0, v1);
            *(float2*)(out + (size_t)(r0 + 8) * N + c0) = make_float2(v2, v3);
        }
    }
}

__global__ __launch_bounds__(256) void hm_gemm_kernel(
    const __nv_bfloat16* __restrict__ Ah, const __nv_bfloat16* __restrict__ Al,
    const __nv_bfloat16* __restrict__ Bh, const __nv_bfloat16* __restrict__ Bl,
    const float* __restrict__ bias, const float* __restrict__ resid,
    float* __restrict__ out, int N, int K, int relu)
{
    extern __shared__ char sm[];
    hm_core(Ah, Al, Bh, Bl, bias, resid, out, N, K, relu,
            blockIdx.y, blockIdx.x, sm);
}

__global__ __launch_bounds__(256) void hm_qkv_kernel(
    const __nv_bfloat16* __restrict__ Ah, const __nv_bfloat16* __restrict__ Al,
    const __nv_bfloat16* __restrict__ Qh, const __nv_bfloat16* __restrict__ Ql,
    const __nv_bfloat16* __restrict__ Kh, const __nv_bfloat16* __restrict__ Kl,
    const __nv_bfloat16* __restrict__ Vh, const __nv_bfloat16* __restrict__ Vl,
    float* __restrict__ q, float* __restrict__ k, float* __restrict__ v)
{
    extern __shared__ char sm[];
    const int mat = blockIdx.x >> 3;
    const int bn  = blockIdx.x & 7;
    const __nv_bfloat16* Bh = (mat == 0) ? Qh : (mat == 1) ? Kh : Vh;
    const __nv_bfloat16* Bl = (mat == 0) ? Ql : (mat == 1) ? Kl : Vl;
    float* out = (mat == 0) ? q : (mat == 1) ? k : v;
    hm_core(Ah, Al, Bh, Bl, nullptr, nullptr, out, CC, CC, 0,
            blockIdx.y, bn, sm);
}

// ---------------------------------------------------------------------------
// Weight transpose + bf16 split: W[K,N] fp32 -> Wt_hi/Wt_lo [N,K] bf16
// ---------------------------------------------------------------------------
__global__ __launch_bounds__(256) void wsplit_kernel(
    const float* __restrict__ W, __nv_bfloat16* __restrict__ th,
    __nv_bfloat16* __restrict__ tl, int K, int N)
{
    __shared__ float tile[32][33];
    const int k0 = blockIdx.y << 5, n0 = blockIdx.x << 5;
    const int tr = threadIdx.x >> 3, tc4 = (threadIdx.x & 7) << 2;
    float4 v = *(const float4*)(W + (size_t)(k0 + tr) * N + n0 + tc4);
    tile[tr][tc4+0] = v.x; tile[tr][tc4+1] = v.y;
    tile[tr][tc4+2] = v.z; tile[tr][tc4+3] = v.w;
    __syncthreads();
    #pragma unroll
    for (int i = 0; i < 4; i++) {
        const float x = tile[tc4 + i][tr];
        const __nv_bfloat16 h = __float2bfloat16(x);
        const __nv_bfloat16 l = __float2bfloat16(x - __bfloat162float(h));
        const size_t oi = (size_t)(n0 + tr) * K + k0 + tc4 + i;
        th[oi] = h; tl[oi] = l;
    }
}

// ---------------------------------------------------------------------------
// Elementwise fp32 -> bf16 hi/lo split
// ---------------------------------------------------------------------------
__global__ __launch_bounds__(256) void cvt_split_kernel(
    const float* __restrict__ in, __nv_bfloat16* __restrict__ hi,
    __nv_bfloat16* __restrict__ lo)
{
    const int i = blockIdx.x * 256 + threadIdx.x;
    float4 v = ((const float4*)in)[i];
    __nv_bfloat16 h0 = __float2bfloat16(v.x), h1 = __float2bfloat16(v.y);
    __nv_bfloat16 h2 = __float2bfloat16(v.z), h3 = __float2bfloat16(v.w);
    __nv_bfloat16 l0 = __float2bfloat16(v.x - __bfloat162float(h0));
    __nv_bfloat16 l1 = __float2bfloat16(v.y - __bfloat162float(h1));
    __nv_bfloat16 l2 = __float2bfloat16(v.z - __bfloat162float(h2));
    __nv_bfloat16 l3 = __float2bfloat16(v.w - __bfloat162float(h3));
    ((__nv_bfloat162*)hi)[2*i]   = __halves2bfloat162(h0, h1);
    ((__nv_bfloat162*)hi)[2*i+1] = __halves2bfloat162(h2, h3);
    ((__nv_bfloat162*)lo)[2*i]   = __halves2bfloat162(l0, l1);
    ((__nv_bfloat162*)lo)[2*i+1] = __halves2bfloat162(l2, l3);
}

// ---------------------------------------------------------------------------
// LayerNorm fused with bf16 hi/lo split output
// ---------------------------------------------------------------------------
__global__ __launch_bounds__(256) void ln_split_kernel(
    const float* __restrict__ x, const float* __restrict__ w,
    const float* __restrict__ bb, __nv_bfloat16* __restrict__ hi,
    __nv_bfloat16* __restrict__ lo)
{
    const int row = blockIdx.x;
    const int tid = threadIdx.x;
    const float* xr = x + (size_t)row * CC;
    float4 xv = ((const float4*)xr)[tid];

    float s  = xv.x + xv.y + xv.z + xv.w;
    float sq = xv.x*xv.x + xv.y*xv.y + xv.z*xv.z + xv.w*xv.w;
    #pragma unroll
    for (int m = 16; m > 0; m >>= 1) {
        s  += __shfl_xor_sync(0xffffffffu, s,  m);
        sq += __shfl_xor_sync(0xffffffffu, sq, m);
    }
    __shared__ float ss[8], ssq[8];
    const int lane = tid & 31, wid = tid >> 5;
    if (lane == 0) { ss[wid] = s; ssq[wid] = sq; }
    __syncthreads();
    float ts = 0.f, tsq = 0.f;
    #pragma unroll
    for (int i = 0; i < 8; i++) { ts += ss[i]; tsq += ssq[i]; }

    const float mu  = ts * (1.0f / CC);
    const float var = tsq * (1.0f / CC) - mu * mu;
    const float rs  = rsqrtf(var + 1e-5f);

    float4 wv = ((const float4*)w)[tid];
    float4 bv = ((const float4*)bb)[tid];
    float o0 = (xv.x - mu) * rs * wv.x + bv.x;
    float o1 = (xv.y - mu) * rs * wv.y + bv.y;
    float o2 = (xv.z - mu) * rs * wv.z + bv.z;
    float o3 = (xv.w - mu) * rs * wv.w + bv.w;

    __nv_bfloat16 h0 = __float2bfloat16(o0), h1 = __float2bfloat16(o1);
    __nv_bfloat16 h2 = __float2bfloat16(o2), h3 = __float2bfloat16(o3);
    __nv_bfloat16 l0 = __float2bfloat16(o0 - __bfloat162float(h0));
    __nv_bfloat16 l1 = __float2bfloat16(o1 - __bfloat162float(h1));
    __nv_bfloat16 l2 = __float2bfloat16(o2 - __bfloat162float(h2));
    __nv_bfloat16 l3 = __float2bfloat16(o3 - __bfloat162float(h3));
    __nv_bfloat162* hp = (__nv_bfloat162*)(hi + (size_t)row * CC);
    __nv_bfloat162* lp = (__nv_bfloat162*)(lo + (size_t)row * CC);
    hp[2*tid]   = __halves2bfloat162(h0, h1);
    hp[2*tid+1] = __halves2bfloat162(h2, h3);
    lp[2*tid]   = __halves2bfloat162(l0, l1);
    lp[2*tid+1] = __halves2bfloat162(l2, l3);
}

// ---------------------------------------------------------------------------
// Flash-attention (causal), fp32 SIMT — unchanged from the 3032us baseline.
// ---------------------------------------------------------------------------
__global__ __launch_bounds__(256) void attn_kernel(
    const float* __restrict__ Q, const float* __restrict__ K,
    const float* __restrict__ V, float* __restrict__ O)
{
    extern __shared__ char sm[];
    float* smf = (float*)sm;
    float* Qs  = smf;            // 64*64
    float* KPs = smf + 4096;     // 64*65
    float* Vs  = KPs + 4160;     // 64*64

    const int tid = threadIdx.x;
    const int tx = tid & 15, ty = tid >> 4;
    const int qb = blockIdx.x, h = blockIdx.y, b = blockIdx.z;

    const size_t base = (size_t)b * TT * CC + (size_t)h * HDD;
    const float* Qb = Q + base;
    const float* Kb = K + base;
    const float* Vb = V + base;

    for (int s = tid; s < 64 * 16; s += 256) {
        int r = s >> 4, c4 = (s & 15) << 2;
        *(float4*)(Qs + r * 64 + c4) =
            *(const float4*)(Qb + (size_t)(qb * 64 + r) * CC + c4);
    }

    float m_i[4], l_i[4], oacc[4][4];
    #pragma unroll
    for (int i = 0; i < 4; i++) {
        m_i[i] = -1e30f; l_i[i] = 0.f;
        #pragma unroll
        for (int j = 0; j < 4; j++) oacc[i][j] = 0.f;
    }

    for (int kb = 0; kb <= qb; kb++) {
        __syncthreads();
        for (int s = tid; s < 64 * 16; s += 256) {
            int r = s >> 4, c4 = (s & 15) << 2;
            float4 kv4 = *(const float4*)(Kb + (size_t)(kb * 64 + r) * CC + c4);
            float* kp = KPs + r * 65 + c4;
            kp[0] = kv4.x; kp[1] = kv4.y; kp[2] = kv4.z; kp[3] = kv4.w;
            *(float4*)(Vs + r * 64 + c4) =
                *(const float4*)(Vb + (size_t)(kb * 64 + r) * CC + c4);
        }
        __syncthreads();

        float sv[4][4];
        #pragma unroll
        for (int i = 0; i < 4; i++)
            #pragma unroll
            for (int j = 0; j < 4; j++) sv[i][j] = 0.f;

        for (int d = 0; d < 64; d++) {
            float qr[4], kr[4];
            #pragma unroll
            for (int i = 0; i < 4; i++) qr[i] = Qs[(ty * 4 + i) * 64 + d];
            #pragma unroll
            for (int j = 0; j < 4; j++) kr[j] = KPs[(tx * 4 + j) * 65 + d];
            #pragma unroll
            for (int i = 0; i < 4; i++)
                #pragma unroll
                for (int j = 0; j < 4; j++) sv[i][j] += qr[i] * kr[j];
        }

        const float scale = 0.125f;
        const int qrow0 = qb * 64 + ty * 4;
        const int kcol0 = kb * 64 + tx * 4;
        const bool diag = (kb == qb);
        #pragma unroll
        for (int i = 0; i < 4; i++)
            #pragma unroll
            for (int j = 0; j < 4; j++) {
                float val = sv[i][j] * scale;
                if (diag && (kcol0 + j > qrow0 + i)) val = -1e30f;
                sv[i][j] = val;
            }

        #pragma unroll
        for (int i = 0; i < 4; i++) {
            float rm = fmaxf(fmaxf(sv[i][0], sv[i][1]), fmaxf(sv[i][2], sv[i][3]));
            #pragma unroll
            for (int msk = 1; msk < 16; msk <<= 1)
                rm = fmaxf(rm, __shfl_xor_sync(0xffffffffu, rm, msk));
            const float mnew = fmaxf(m_i[i], rm);
            const float alpha = __expf(m_i[i] - mnew);
            l_i[i] *= alpha;
            #pragma unroll
            for (int j = 0; j < 4; j++) oacc[i][j] *= alpha;
            float rs = 0.f;
            #pragma unroll
            for (int j = 0; j < 4; j++) {
                sv[i][j] = __expf(sv[i][j] - mnew);
                rs += sv[i][j];
            }
            #pragma unroll
            for (int msk = 1; msk < 16; msk <<= 1)
                rs += __shfl_xor_sync(0xffffffffu, rs, msk);
            l_i[i] += rs;
            m_i[i] = mnew;
        }

        __syncthreads();
        #pragma unroll
        for (int i = 0; i < 4; i++)
            #pragma unroll
            for (int j = 0; j < 4; j++)
                KPs[(ty * 4 + i) * 65 + tx * 4 + j] = sv[i][j];
        __syncthreads();

        for (int d = 0; d < 64; d++) {
            float pr[4], vr[4];
            #pragma unroll
            for (int i = 0; i < 4; i++) pr[i] = KPs[(ty * 4 + i) * 65 + d];
            #pragma unroll
            for (int j = 0; j < 4; j++) vr[j] = Vs[d * 64 + tx * 4 + j];
            #pragma unroll
            for (int i = 0; i < 4; i++)
                #pragma unroll
                for (int j = 0; j < 4; j++) oacc[i][j] += pr[i] * vr[j];
        }
    }

    float* Ob = O + base;
    #pragma unroll
    for (int i = 0; i < 4; i++) {
        const float inv = 1.0f / l_i[i];
        float4 ov = make_float4(oacc[i][0] * inv, oacc[i][1] * inv,
                                oacc[i][2] * inv, oacc[i][3] * inv);
        *(float4*)(Ob + (size_t)(qb * 64 + ty * 4 + i) * CC + tx * 4) = ov;
    }
}

// ---------------------------------------------------------------------------
// Launch
// ---------------------------------------------------------------------------
extern "C" void kernel_launch(void* const* d_in, const int* in_sizes, int n_in,
                              void* d_out, int out_size)
{
    const float* x     = (const float*)d_in[0];
    const float* ln1_w = (const float*)d_in[1];
    const float* ln1_b = (const float*)d_in[2];
    const float* Wq    = (const float*)d_in[3];
    const float* Wk    = (const float*)d_in[4];
    const float* Wv    = (const float*)d_in[5];
    const float* Wp    = (const float*)d_in[6];
    const float* bp    = (const float*)d_in[7];
    const float* ln2_w = (const float*)d_in[8];
    const float* ln2_b = (const float*)d_in[9];
    const float* W1    = (const float*)d_in[10];
    const float* b1    = (const float*)d_in[11];
    const float* W2    = (const float*)d_in[12];
    const float* b2    = (const float*)d_in[13];

    float *q, *k, *v, *o, *x1, *ff;
    cudaGetSymbolAddress((void**)&q,  g_q);
    cudaGetSymbolAddress((void**)&k,  g_k);
    cudaGetSymbolAddress((void**)&v,  g_v);
    cudaGetSymbolAddress((void**)&o,  g_o);
    cudaGetSymbolAddress((void**)&x1, g_x1);
    cudaGetSymbolAddress((void**)&ff, g_ff);

    __nv_bfloat16 *ah, *al;
    __nv_bfloat16 *wqh, *wql, *wkh, *wkl, *wvh, *wvl, *wph, *wpl;
    __nv_bfloat16 *w1h, *w1l, *w2h, *w2l;
    cudaGetSymbolAddress((void**)&ah,  g_ah);
    cudaGetSymbolAddress((void**)&al,  g_al);
    cudaGetSymbolAddress((void**)&wqh, g_wqh);
    cudaGetSymbolAddress((void**)&wql, g_wql);
    cudaGetSymbolAddress((void**)&wkh, g_wkh);
    cudaGetSymbolAddress((void**)&wkl, g_wkl);
    cudaGetSymbolAddress((void**)&wvh, g_wvh);
    cudaGetSymbolAddress((void**)&wvl, g_wvl);
    cudaGetSymbolAddress((void**)&wph, g_wph);
    cudaGetSymbolAddress((void**)&wpl, g_wpl);
    cudaGetSymbolAddress((void**)&w1h, g_w1h);
    cudaGetSymbolAddress((void**)&w1l, g_w1l);
    cudaGetSymbolAddress((void**)&w2h, g_w2h);
    cudaGetSymbolAddress((void**)&w2l, g_w2l);

    cudaFuncSetAttribute(hm_gemm_kernel,
                         cudaFuncAttributeMaxDynamicSharedMemorySize, HM_SMEM);
    cudaFuncSetAttribute(hm_qkv_kernel,
                         cudaFuncAttributeMaxDynamicSharedMemorySize, HM_SMEM);

    // 0. Weight transpose + split
    wsplit_kernel<<<dim3(CC/32,  CC/32),  256>>>(Wq, wqh, wql, CC, CC);
    wsplit_kernel<<<dim3(CC/32,  CC/32),  256>>>(Wk, wkh, wkl, CC, CC);
    wsplit_kernel<<<dim3(CC/32,  CC/32),  256>>>(Wv, wvh, wvl, CC, CC);
    wsplit_kernel<<<dim3(CC/32,  CC/32),  256>>>(Wp, wph, wpl, CC, CC);
    wsplit_kernel<<<dim3(FFF/32, CC/32),  256>>>(W1, w1h, w1l, CC, FFF);
    wsplit_kernel<<<dim3(CC/32,  FFF/32), 256>>>(W2, w2h, w2l, FFF, CC);

    // 1. h = LN1(x), split to bf16 hi/lo
    ln_split_kernel<<<MM, 256>>>(x, ln1_w, ln1_b, ah, al);

    // 2. q/k/v = h @ W{q,k,v}  (HMMA, fused 3-matrix launch)
    hm_qkv_kernel<<<dim3(24, MM/128), 256, HM_SMEM>>>(
        ah, al, wqh, wql, wkh, wkl, wvh, wvl, q, k, v);

    // 3. o = causal_attention(q, k, v)
    const size_t attn_smem = (4096 + 4160 + 4096) * sizeof(float);
    cudaFuncSetAttribute(attn_kernel,
                         cudaFuncAttributeMaxDynamicSharedMemorySize,
                         (int)attn_smem);
    attn_kernel<<<dim3(TT/64, NHH, BB), 256, attn_smem>>>(q, k, v, o);

    // 4. x1 = x + o @ Wp + bp
    cvt_split_kernel<<<(MM*CC)/1024, 256>>>(o, ah, al);
    hm_gemm_kernel<<<dim3(CC/128, MM/128), 256, HM_SMEM>>>(
        ah, al, wph, wpl, bp, x, x1, CC, CC, 0);

    // 5. h2 = LN2(x1), split
    ln_split_kernel<<<MM, 256>>>(x1, ln2_w, ln2_b, ah, al);

    // 6. ff = relu(h2 @ W1 + b1)
    hm_gemm_kernel<<<dim3(FFF/128, MM/128), 256, HM_SMEM>>>(
        ah, al, w1h, w1l, b1, nullptr, ff, FFF, CC, 1);

    // 7. out = x1 + ff @ W2 + b2
    cvt_split_kernel<<<(MM*FFF)/1024, 256>>>(ff, ah, al);
    hm_gemm_kernel<<<dim3(CC/128, MM/128), 256, HM_SMEM>>>(
        ah, al, w2h, w2l, b2, x1, (float*)d_out, CC, FFF, 0);
}

// round 17
// speedup vs baseline: 2.1556x; 1.0252x over previous
#include <cuda_runtime.h>
#include <cuda_bf16.h>
#include <cstddef>

// Problem constants
#define BB 2
#define TT 2048
#define CC 1024
#define NHH 16
#define HDD 64
#define FFF 4096
#define MM (BB*TT)   // 4096

// ---------------------------------------------------------------------------
// Scratch (static device arrays — allocation-free per harness rules)
// ---------------------------------------------------------------------------
__device__ float g_q [MM*CC];
__device__ float g_k [MM*CC];
__device__ float g_v [MM*CC];
__device__ float g_x1[MM*CC];

// Activation bf16 split buffers
__device__ __nv_bfloat16 g_ah[MM*CC];   // h / attn-out / h2 (reused)
__device__ __nv_bfloat16 g_al[MM*CC];
__device__ __nv_bfloat16 g_bh[MM*FFF];  // relu FFN hidden
__device__ __nv_bfloat16 g_bl[MM*FFF];

// Weight bf16 split, TRANSPOSED to [N,K] K-major
__device__ __nv_bfloat16 g_wqh[CC*CC],  g_wql[CC*CC];
__device__ __nv_bfloat16 g_wkh[CC*CC],  g_wkl[CC*CC];
__device__ __nv_bfloat16 g_wvh[CC*CC],  g_wvl[CC*CC];
__device__ __nv_bfloat16 g_wph[CC*CC],  g_wpl[CC*CC];
__device__ __nv_bfloat16 g_w1h[FFF*CC], g_w1l[FFF*CC];
__device__ __nv_bfloat16 g_w2h[CC*FFF], g_w2l[CC*FFF];

// ---------------------------------------------------------------------------
// HMMA helpers (sm_80-era PTX; legal on plain sm_103 target)
// ---------------------------------------------------------------------------
__device__ __forceinline__ unsigned smem_u32(const void* p) {
    unsigned a;
    asm("{ .reg .u64 t; cvta.to.shared.u64 t, %1; cvt.u32.u64 %0, t; }"
        : "=r"(a) : "l"(p));
    return a;
}
__device__ __forceinline__ void ldm_x4(unsigned* r, unsigned addr) {
    asm volatile("ldmatrix.sync.aligned.m8n8.x4.shared.b16 {%0,%1,%2,%3}, [%4];"
        : "=r"(r[0]), "=r"(r[1]), "=r"(r[2]), "=r"(r[3]) : "r"(addr));
}
__device__ __forceinline__ void mma_bf16(float* d, const unsigned* a,
                                         const unsigned* b) {
    asm volatile(
        "mma.sync.aligned.m16n8k16.row.col.f32.bf16.bf16.f32 "
        "{%0,%1,%2,%3}, {%4,%5,%6,%7}, {%8,%9}, {%0,%1,%2,%3};"
        : "+f"(d[0]), "+f"(d[1]), "+f"(d[2]), "+f"(d[3])
        : "r"(a[0]), "r"(a[1]), "r"(a[2]), "r"(a[3]), "r"(b[0]), "r"(b[1]));
}
__device__ __forceinline__ unsigned pack2u(__nv_bfloat16 a, __nv_bfloat16 b) {
    return ((unsigned)__bfloat16_as_ushort(b) << 16) |
           (unsigned)__bfloat16_as_ushort(a);
}
__device__ __forceinline__ unsigned pack_hi(float a, float b) {
    return pack2u(__float2bfloat16(a), __float2bfloat16(b));
}
__device__ __forceinline__ unsigned pack_lo(float a, float b) {
    const __nv_bfloat16 ha = __float2bfloat16(a), hb = __float2bfloat16(b);
    return pack2u(__float2bfloat16(a - __bfloat162float(ha)),
                  __float2bfloat16(b - __bfloat162float(hb)));
}

// ---------------------------------------------------------------------------
// HMMA GEMM: out = split_A[M,K] @ split_B[N,K]^T (+bias)(+resid)(relu)
// 128x128 CTA tile, BK=32, 8 warps (32m x 64n each), bf16x3 split passes.
// Optional split-bf16 output (outh/outl) instead of fp32.
// ---------------------------------------------------------------------------
#define TSB 40                         // tile row stride in bf16
#define TILE_B (128 * TSB * 2)         // 10240 bytes per tile
#define BUF_B  (4 * TILE_B)
#define HM_SMEM (2 * BUF_B)            // 81920 bytes

__device__ __forceinline__ void hm_store(
    char* buf, const uint4* va, int tid)
{
    #pragma unroll
    for (int it = 0; it < 2; it++) {
        const int idx = tid + it * 256;
        const int r   = idx >> 2;
        const int c8  = (idx & 3) << 3;
        const int off = (r * TSB + c8) * 2;
        *(uint4*)(buf + off)              = va[it];
        *(uint4*)(buf + TILE_B + off)     = va[2 + it];
        *(uint4*)(buf + 2 * TILE_B + off) = va[4 + it];
        *(uint4*)(buf + 3 * TILE_B + off) = va[6 + it];
    }
}

__device__ __forceinline__ void hm_ldg(
    uint4* va, int k0,
    const __nv_bfloat16* __restrict__ Ah, const __nv_bfloat16* __restrict__ Al,
    int arow0,
    const __nv_bfloat16* __restrict__ Bh, const __nv_bfloat16* __restrict__ Bl,
    int brow0, int K, int tid)
{
    #pragma unroll
    for (int it = 0; it < 2; it++) {
        const int idx = tid + it * 256;
        const int r   = idx >> 2;
        const int c8  = (idx & 3) << 3;
        const size_t ga = (size_t)(arow0 + r) * K + k0 + c8;
        const size_t gb = (size_t)(brow0 + r) * K + k0 + c8;
        va[it]     = *(const uint4*)(Ah + ga);
        va[2 + it] = *(const uint4*)(Al + ga);
        va[4 + it] = *(const uint4*)(Bh + gb);
        va[6 + it] = *(const uint4*)(Bl + gb);
    }
}

__device__ void hm_core(
    const __nv_bfloat16* __restrict__ Ah, const __nv_bfloat16* __restrict__ Al,
    const __nv_bfloat16* __restrict__ Bh, const __nv_bfloat16* __restrict__ Bl,
    const float* __restrict__ bias, const float* __restrict__ resid,
    float* __restrict__ out,
    __nv_bfloat16* __restrict__ outh, __nv_bfloat16* __restrict__ outl,
    int N, int K, int relu, int bm, int bn, char* sm)
{
    const int tid  = threadIdx.x;
    const int wid  = tid >> 5, lane = tid & 31;
    const int wm   = wid & 3;
    const int wn   = wid >> 2;
    const unsigned sbase = smem_u32(sm);
    const int arow0 = bm * 128, brow0 = bn * 128;

    float acc[2][8][4];
    #pragma unroll
    for (int i = 0; i < 2; i++)
        #pragma unroll
        for (int j = 0; j < 8; j++)
            #pragma unroll
            for (int c = 0; c < 4; c++) acc[i][j][c] = 0.f;

    uint4 va[8];
    hm_ldg(va, 0, Ah, Al, arow0, Bh, Bl, brow0, K, tid);
    hm_store(sm, va, tid);
    __syncthreads();

    const int l8 = lane & 7, q = lane >> 3;
    const int amr = (q & 1) * 8 + l8;
    const int akc = (q >> 1) * 8;
    const int bnr = (q >> 1) * 8 + l8;
    const int bkc = (q & 1) * 8;

    const int nt_chunks = K >> 5;
    int cur = 0;
    for (int t = 0; t < nt_chunks; t++) {
        if (t + 1 < nt_chunks)
            hm_ldg(va, (t + 1) << 5, Ah, Al, arow0, Bh, Bl, brow0, K, tid);

        const unsigned ab  = sbase + cur * BUF_B;
        const unsigned alb = ab + TILE_B;
        const unsigned bhb = ab + 2 * TILE_B;
        const unsigned blb = ab + 3 * TILE_B;

        #pragma unroll
        for (int ks = 0; ks < 2; ks++) {
            unsigned Afh[2][4], Afl[2][4];
            #pragma unroll
            for (int mt = 0; mt < 2; mt++) {
                const int row = wm * 32 + mt * 16 + amr;
                const int off = (row * TSB + ks * 16 + akc) * 2;
                ldm_x4(Afh[mt], ab  + off);
                ldm_x4(Afl[mt], alb + off);
            }
            #pragma unroll
            for (int np = 0; np < 4; np++) {
                const int nrow = wn * 64 + np * 16 + bnr;
                const int off  = (nrow * TSB + ks * 16 + bkc) * 2;
                unsigned Bfh[4], Bfl[4];
                ldm_x4(Bfh, bhb + off);
                ldm_x4(Bfl, blb + off);
                #pragma unroll
                for (int mt = 0; mt < 2; mt++) {
                    mma_bf16(acc[mt][np*2],   Afh[mt], Bfh);
                    mma_bf16(acc[mt][np*2+1], Afh[mt], Bfh + 2);
                    mma_bf16(acc[mt][np*2],   Afh[mt], Bfl);
                    mma_bf16(acc[mt][np*2+1], Afh[mt], Bfl + 2);
                    mma_bf16(acc[mt][np*2],   Afl[mt], Bfh);
                    mma_bf16(acc[mt][np*2+1], Afl[mt], Bfh + 2);
                }
            }
        }

        if (t + 1 < nt_chunks) {
            const int nxt = cur ^ 1;
            hm_store(sm + nxt * BUF_B, va, tid);
            __syncthreads();
            cur = nxt;
        }
    }

    // epilogue
    const int colb = bn * 128 + wn * 64;
    #pragma unroll
    for (int mt = 0; mt < 2; mt++) {
        const int r0 = arow0 + wm * 32 + mt * 16 + (lane >> 2);
        #pragma unroll
        for (int nt = 0; nt < 8; nt++) {
            const int c0 = colb + nt * 8 + (lane & 3) * 2;
            float* cc = acc[mt][nt];
            float v0 = cc[0], v1 = cc[1], v2 = cc[2], v3 = cc[3];
            if (bias) {
                const float b0 = bias[c0], b1 = bias[c0 + 1];
                v0 += b0; v1 += b1; v2 += b0; v3 += b1;
            }
            if (resid) {
                const float2 ra = *(const float2*)(resid + (size_t)r0 * N + c0);
                const float2 rb = *(const float2*)(resid + (size_t)(r0+8) * N + c0);
                v0 += ra.x; v1 += ra.y; v2 += rb.x; v3 += rb.y;
            }
            if (relu) {
                v0 = fmaxf(v0, 0.f); v1 = fmaxf(v1, 0.f);
                v2 = fmaxf(v2, 0.f); v3 = fmaxf(v3, 0.f);
            }
            if (outh) {
                *(unsigned*)(outh + (size_t)r0 * N + c0)       = pack_hi(v0, v1);
                *(unsigned*)(outh + (size_t)(r0 + 8) * N + c0) = pack_hi(v2, v3);
                *(unsigned*)(outl + (size_t)r0 * N + c0)       = pack_lo(v0, v1);
                *(unsigned*)(outl + (size_t)(r0 + 8) * N + c0) = pack_lo(v2, v3);
            } else {
                *(float2*)(out + (size_t)r0 * N + c0)       = make_float2(v0, v1);
                *(float2*)(out + (size_t)(r0 + 8) * N + c0) = make_float2(v2, v3);
            }
        }
    }
}

__global__ __launch_bounds__(256) void hm_gemm_kernel(
    const __nv_bfloat16* __restrict__ Ah, const __nv_bfloat16* __restrict__ Al,
    const __nv_bfloat16* __restrict__ Bh, const __nv_bfloat16* __restrict__ Bl,
    const float* __restrict__ bias, const float* __restrict__ resid,
    float* __restrict__ out,
    __nv_bfloat16* __restrict__ outh, __nv_bfloat16* __restrict__ outl,
    int N, int K, int relu)
{
    extern __shared__ char sm[];
    hm_core(Ah, Al, Bh, Bl, bias, resid, out, outh, outl, N, K, relu,
            blockIdx.y, blockIdx.x, sm);
}

__global__ __launch_bounds__(256) void hm_qkv_kernel(
    const __nv_bfloat16* __restrict__ Ah, const __nv_bfloat16* __restrict__ Al,
    const __nv_bfloat16* __restrict__ Qh, const __nv_bfloat16* __restrict__ Ql,
    const __nv_bfloat16* __restrict__ Kh, const __nv_bfloat16* __restrict__ Kl,
    const __nv_bfloat16* __restrict__ Vh, const __nv_bfloat16* __restrict__ Vl,
    float* __restrict__ q, float* __restrict__ k, float* __restrict__ v)
{
    extern __shared__ char sm[];
    const int mat = blockIdx.x >> 3;
    const int bn  = blockIdx.x & 7;
    const __nv_bfloat16* Bh = (mat == 0) ? Qh : (mat == 1) ? Kh : Vh;
    const __nv_bfloat16* Bl = (mat == 0) ? Ql : (mat == 1) ? Kl : Vl;
    float* out = (mat == 0) ? q : (mat == 1) ? k : v;
    hm_core(Ah, Al, Bh, Bl, nullptr, nullptr, out, nullptr, nullptr,
            CC, CC, 0, blockIdx.y, bn, sm);
}

// ---------------------------------------------------------------------------
// Weight transpose + bf16 split (batched): W[K,N] fp32 -> [N,K] bf16 hi/lo
// ---------------------------------------------------------------------------
__device__ __forceinline__ void wsplit_tile(
    const float* __restrict__ W, __nv_bfloat16* __restrict__ th,
    __nv_bfloat16* __restrict__ tl, int K, int N, int bx, int by)
{
    __shared__ float tile[32][33];
    const int k0 = by << 5, n0 = bx << 5;
    const int tr = threadIdx.x >> 3, tc4 = (threadIdx.x & 7) << 2;
    float4 v = *(const float4*)(W + (size_t)(k0 + tr) * N + n0 + tc4);
    tile[tr][tc4+0] = v.x; tile[tr][tc4+1] = v.y;
    tile[tr][tc4+2] = v.z; tile[tr][tc4+3] = v.w;
    __syncthreads();
    #pragma unroll
    for (int i = 0; i < 4; i++) {
        const float x = tile[tc4 + i][tr];
        const __nv_bfloat16 h = __float2bfloat16(x);
        const __nv_bfloat16 l = __float2bfloat16(x - __bfloat162float(h));
        const size_t oi = (size_t)(n0 + tr) * K + k0 + tc4 + i;
        th[oi] = h; tl[oi] = l;
    }
}

// Wq, Wk, Wv (each CC x CC): 3 x 1024 blocks
__global__ __launch_bounds__(256) void wsplit_qkv_kernel(
    const float* __restrict__ Wq, const float* __restrict__ Wk,
    const float* __restrict__ Wv,
    __nv_bfloat16* __restrict__ qh, __nv_bfloat16* __restrict__ ql,
    __nv_bfloat16* __restrict__ kh, __nv_bfloat16* __restrict__ kl,
    __nv_bfloat16* __restrict__ vh, __nv_bfloat16* __restrict__ vl)
{
    const int b = blockIdx.x, sel = b >> 10, local = b & 1023;
    const float* W = (sel == 0) ? Wq : (sel == 1) ? Wk : Wv;
    __nv_bfloat16* th = (sel == 0) ? qh : (sel == 1) ? kh : vh;
    __nv_bfloat16* tl = (sel == 0) ? ql : (sel == 1) ? kl : vl;
    wsplit_tile(W, th, tl, CC, CC, local & 31, local >> 5);
}

// Wp (CCxCC, 1024 blk) + W1 (CCxFFF, 4096 blk) + W2 (FFFxCC, 4096 blk)
__global__ __launch_bounds__(256) void wsplit_pw_kernel(
    const float* __restrict__ Wp, const float* __restrict__ W1,
    const float* __restrict__ W2,
    __nv_bfloat16* __restrict__ ph, __nv_bfloat16* __restrict__ pl,
    __nv_bfloat16* __restrict__ h1, __nv_bfloat16* __restrict__ l1,
    __nv_bfloat16* __restrict__ h2, __nv_bfloat16* __restrict__ l2)
{
    const int b = blockIdx.x;
    if (b < 1024) {
        wsplit_tile(Wp, ph, pl, CC, CC, b & 31, b >> 5);
    } else if (b < 5120) {
        const int local = b - 1024;           // N=FFF -> 128 col tiles
        wsplit_tile(W1, h1, l1, CC, FFF, local & 127, local >> 7);
    } else {
        const int local = b - 5120;           // N=CC -> 32 col tiles
        wsplit_tile(W2, h2, l2, FFF, CC, local & 31, local >> 5);
    }
}

// ---------------------------------------------------------------------------
// LayerNorm fused with bf16 hi/lo split output
// ---------------------------------------------------------------------------
__global__ __launch_bounds__(256) void ln_split_kernel(
    const float* __restrict__ x, const float* __restrict__ w,
    const float* __restrict__ bb, __nv_bfloat16* __restrict__ hi,
    __nv_bfloat16* __restrict__ lo)
{
    const int row = blockIdx.x;
    const int tid = threadIdx.x;
    const float* xr = x + (size_t)row * CC;
    float4 xv = ((const float4*)xr)[tid];

    float s  = xv.x + xv.y + xv.z + xv.w;
    float sq = xv.x*xv.x + xv.y*xv.y + xv.z*xv.z + xv.w*xv.w;
    #pragma unroll
    for (int m = 16; m > 0; m >>= 1) {
        s  += __shfl_xor_sync(0xffffffffu, s,  m);
        sq += __shfl_xor_sync(0xffffffffu, sq, m);
    }
    __shared__ float ss[8], ssq[8];
    const int lane = tid & 31, wid = tid >> 5;
    if (lane == 0) { ss[wid] = s; ssq[wid] = sq; }
    __syncthreads();
    float ts = 0.f, tsq = 0.f;
    #pragma unroll
    for (int i = 0; i < 8; i++) { ts += ss[i]; tsq += ssq[i]; }

    const float mu  = ts * (1.0f / CC);
    const float var = tsq * (1.0f / CC) - mu * mu;
    const float rs  = rsqrtf(var + 1e-5f);

    float4 wv = ((const float4*)w)[tid];
    float4 bv = ((const float4*)bb)[tid];
    float o0 = (xv.x - mu) * rs * wv.x + bv.x;
    float o1 = (xv.y - mu) * rs * wv.y + bv.y;
    float o2 = (xv.z - mu) * rs * wv.z + bv.z;
    float o3 = (xv.w - mu) * rs * wv.w + bv.w;

    unsigned* hp = (unsigned*)(hi + (size_t)row * CC);
    unsigned* lp = (unsigned*)(lo + (size_t)row * CC);
    hp[2*tid]   = pack_hi(o0, o1);
    hp[2*tid+1] = pack_hi(o2, o3);
    lp[2*tid]   = pack_lo(o0, o1);
    lp[2*tid+1] = pack_lo(o2, o3);
}

// ---------------------------------------------------------------------------
// Flash-attention (causal), fp32 SIMT; writes bf16 hi/lo split output.
// ---------------------------------------------------------------------------
__global__ __launch_bounds__(256) void attn_kernel(
    const float* __restrict__ Q, const float* __restrict__ K,
    const float* __restrict__ V,
    __nv_bfloat16* __restrict__ OH, __nv_bfloat16* __restrict__ OL)
{
    extern __shared__ char sm[];
    float* smf = (float*)sm;
    float* Qs  = smf;            // 64*64
    float* KPs = smf + 4096;     // 64*65
    float* Vs  = KPs + 4160;     // 64*64

    const int tid = threadIdx.x;
    const int tx = tid & 15, ty = tid >> 4;
    const int qb = blockIdx.x, h = blockIdx.y, b = blockIdx.z;

    const size_t base = (size_t)b * TT * CC + (size_t)h * HDD;
    const float* Qb = Q + base;
    const float* Kb = K + base;
    const float* Vb = V + base;

    for (int s = tid; s < 64 * 16; s += 256) {
        int r = s >> 4, c4 = (s & 15) << 2;
        *(float4*)(Qs + r * 64 + c4) =
            *(const float4*)(Qb + (size_t)(qb * 64 + r) * CC + c4);
    }

    float m_i[4], l_i[4], oacc[4][4];
    #pragma unroll
    for (int i = 0; i < 4; i++) {
        m_i[i] = -1e30f; l_i[i] = 0.f;
        #pragma unroll
        for (int j = 0; j < 4; j++) oacc[i][j] = 0.f;
    }

    for (int kb = 0; kb <= qb; kb++) {
        __syncthreads();
        for (int s = tid; s < 64 * 16; s += 256) {
            int r = s >> 4, c4 = (s & 15) << 2;
            float4 kv4 = *(const float4*)(Kb + (size_t)(kb * 64 + r) * CC + c4);
            float* kp = KPs + r * 65 + c4;
            kp[0] = kv4.x; kp[1] = kv4.y; kp[2] = kv4.z; kp[3] = kv4.w;
            *(float4*)(Vs + r * 64 + c4) =
                *(const float4*)(Vb + (size_t)(kb * 64 + r) * CC + c4);
        }
        __syncthreads();

        float sv[4][4];
        #pragma unroll
        for (int i = 0; i < 4; i++)
            #pragma unroll
            for (int j = 0; j < 4; j++) sv[i][j] = 0.f;

        for (int d = 0; d < 64; d++) {
            float qr[4], kr[4];
            #pragma unroll
            for (int i = 0; i < 4; i++) qr[i] = Qs[(ty * 4 + i) * 64 + d];
            #pragma unroll
            for (int j = 0; j < 4; j++) kr[j] = KPs[(tx * 4 + j) * 65 + d];
            #pragma unroll
            for (int i = 0; i < 4; i++)
                #pragma unroll
                for (int j = 0; j < 4; j++) sv[i][j] += qr[i] * kr[j];
        }

        const float scale = 0.125f;
        const int qrow0 = qb * 64 + ty * 4;
        const int kcol0 = kb * 64 + tx * 4;
        const bool diag = (kb == qb);
        #pragma unroll
        for (int i = 0; i < 4; i++)
            #pragma unroll
            for (int j = 0; j < 4; j++) {
                float val = sv[i][j] * scale;
                if (diag && (kcol0 + j > qrow0 + i)) val = -1e30f;
                sv[i][j] = val;
            }

        #pragma unroll
        for (int i = 0; i < 4; i++) {
            float rm = fmaxf(fmaxf(sv[i][0], sv[i][1]), fmaxf(sv[i][2], sv[i][3]));
            #pragma unroll
            for (int msk = 1; msk < 16; msk <<= 1)
                rm = fmaxf(rm, __shfl_xor_sync(0xffffffffu, rm, msk));
            const float mnew = fmaxf(m_i[i], rm);
            const float alpha = __expf(m_i[i] - mnew);
            l_i[i] *= alpha;
            #pragma unroll
            for (int j = 0; j < 4; j++) oacc[i][j] *= alpha;
            float rs = 0.f;
            #pragma unroll
            for (int j = 0; j < 4; j++) {
                sv[i][j] = __expf(sv[i][j] - mnew);
                rs += sv[i][j];
            }
            #pragma unroll
            for (int msk = 1; msk < 16; msk <<= 1)
                rs += __shfl_xor_sync(0xffffffffu, rs, msk);
            l_i[i] += rs;
            m_i[i] = mnew;
        }

        __syncthreads();
        #pragma unroll
        for (int i = 0; i < 4; i++)
            #pragma unroll
            for (int j = 0; j < 4; j++)
                KPs[(ty * 4 + i) * 65 + tx * 4 + j] = sv[i][j];
        __syncthreads();

        for (int d = 0; d < 64; d++) {
            float pr[4], vr[4];
            #pragma unroll
            for (int i = 0; i < 4; i++) pr[i] = KPs[(ty * 4 + i) * 65 + d];
            #pragma unroll
            for (int j = 0; j < 4; j++) vr[j] = Vs[d * 64 + tx * 4 + j];
            #pragma unroll
            for (int i = 0; i < 4; i++)
                #pragma unroll
                for (int j = 0; j < 4; j++) oacc[i][j] += pr[i] * vr[j];
        }
    }

    __nv_bfloat16* OHb = OH + base;
    __nv_bfloat16* OLb = OL + base;
    #pragma unroll
    for (int i = 0; i < 4; i++) {
        const float inv = 1.0f / l_i[i];
        const float v0 = oacc[i][0] * inv, v1 = oacc[i][1] * inv;
        const float v2 = oacc[i][2] * inv, v3 = oacc[i][3] * inv;
        const size_t off = (size_t)(qb * 64 + ty * 4 + i) * CC + tx * 4;
        *(unsigned*)(OHb + off)     = pack_hi(v0, v1);
        *(unsigned*)(OHb + off + 2) = pack_hi(v2, v3);
        *(unsigned*)(OLb + off)     = pack_lo(v0, v1);
        *(unsigned*)(OLb + off + 2) = pack_lo(v2, v3);
    }
}

// ---------------------------------------------------------------------------
// Launch.  Order puts the Wp HMMA GEMM at launch #6 (ncu profiles -s 5 -c 1).
// ---------------------------------------------------------------------------
extern "C" void kernel_launch(void* const* d_in, const int* in_sizes, int n_in,
                              void* d_out, int out_size)
{
    const float* x     = (const float*)d_in[0];
    const float* ln1_w = (const float*)d_in[1];
    const float* ln1_b = (const float*)d_in[2];
    const float* Wq    = (const float*)d_in[3];
    const float* Wk    = (const float*)d_in[4];
    const float* Wv    = (const float*)d_in[5];
    const float* Wp    = (const float*)d_in[6];
    const float* bp    = (const float*)d_in[7];
    const float* ln2_w = (const float*)d_in[8];
    const float* ln2_b = (const float*)d_in[9];
    const float* W1    = (const float*)d_in[10];
    const float* b1    = (const float*)d_in[11];
    const float* W2    = (const float*)d_in[12];
    const float* b2    = (const float*)d_in[13];

    float *q, *k, *v, *x1;
    cudaGetSymbolAddress((void**)&q,  g_q);
    cudaGetSymbolAddress((void**)&k,  g_k);
    cudaGetSymbolAddress((void**)&v,  g_v);
    cudaGetSymbolAddress((void**)&x1, g_x1);

    __nv_bfloat16 *ah, *al, *bh, *bl;
    __nv_bfloat16 *wqh, *wql, *wkh, *wkl, *wvh, *wvl, *wph, *wpl;
    __nv_bfloat16 *w1h, *w1l, *w2h, *w2l;
    cudaGetSymbolAddress((void**)&ah,  g_ah);
    cudaGetSymbolAddress((void**)&al,  g_al);
    cudaGetSymbolAddress((void**)&bh,  g_bh);
    cudaGetSymbolAddress((void**)&bl,  g_bl);
    cudaGetSymbolAddress((void**)&wqh, g_wqh);
    cudaGetSymbolAddress((void**)&wql, g_wql);
    cudaGetSymbolAddress((void**)&wkh, g_wkh);
    cudaGetSymbolAddress((void**)&wkl, g_wkl);
    cudaGetSymbolAddress((void**)&wvh, g_wvh);
    cudaGetSymbolAddress((void**)&wvl, g_wvl);
    cudaGetSymbolAddress((void**)&wph, g_wph);
    cudaGetSymbolAddress((void**)&wpl, g_wpl);
    cudaGetSymbolAddress((void**)&w1h, g_w1h);
    cudaGetSymbolAddress((void**)&w1l, g_w1l);
    cudaGetSymbolAddress((void**)&w2h, g_w2h);
    cudaGetSymbolAddress((void**)&w2l, g_w2l);

    cudaFuncSetAttribute(hm_gemm_kernel,
                         cudaFuncAttributeMaxDynamicSharedMemorySize, HM_SMEM);
    cudaFuncSetAttribute(hm_qkv_kernel,
                         cudaFuncAttributeMaxDynamicSharedMemorySize, HM_SMEM);

    // 1. h = LN1(x), split
    ln_split_kernel<<<MM, 256>>>(x, ln1_w, ln1_b, ah, al);

    // 2. QKV weight split (one launch)
    wsplit_qkv_kernel<<<3 * 1024, 256>>>(Wq, Wk, Wv, wqh, wql, wkh, wkl, wvh, wvl);

    // 3. q/k/v = h @ W{q,k,v}
    hm_qkv_kernel<<<dim3(24, MM/128), 256, HM_SMEM>>>(
        ah, al, wqh, wql, wkh, wkl, wvh, wvl, q, k, v);

    // 4. attention -> bf16 split directly into ah/al
    const size_t attn_smem = (4096 + 4160 + 4096) * sizeof(float);
    cudaFuncSetAttribute(attn_kernel,
                         cudaFuncAttributeMaxDynamicSharedMemorySize,
                         (int)attn_smem);
    attn_kernel<<<dim3(TT/64, NHH, BB), 256, attn_smem>>>(q, k, v, ah, al);

    // 5. Wp/W1/W2 weight split (one launch)
    wsplit_pw_kernel<<<1024 + 4096 + 4096, 256>>>(
        Wp, W1, W2, wph, wpl, w1h, w1l, w2h, w2l);

    // 6. x1 = x + attn @ Wp + bp        <-- profiled launch
    hm_gemm_kernel<<<dim3(CC/128, MM/128), 256, HM_SMEM>>>(
        ah, al, wph, wpl, bp, x, x1, nullptr, nullptr, CC, CC, 0);

    // 7. h2 = LN2(x1), split
    ln_split_kernel<<<MM, 256>>>(x1, ln2_w, ln2_b, ah, al);

    // 8. ffn hidden = relu(h2 @ W1 + b1) -> bf16 split directly
    hm_gemm_kernel<<<dim3(FFF/128, MM/128), 256, HM_SMEM>>>(
        ah, al, w1h, w1l, b1, nullptr, nullptr, bh, bl, FFF, CC, 1);

    // 9. out = x1 + ffn @ W2 + b2
    hm_gemm_kernel<<<dim3(CC/128, MM/128), 256, HM_SMEM>>>(
        bh, bl, w2h, w2l, b2, x1, (float*)d_out, nullptr, nullptr, CC, FFF, 0);
}